// round 6
// baseline (speedup 1.0000x reference)
#include <cuda_runtime.h>
#include <cuda_fp16.h>
#include <math.h>
#include <stdint.h>

// Problem constants
#define B_N   16
#define N_TOK 1024
#define DIM_N 768
#define H_N   12
#define QKVD  2304
#define MROWS 16384
#define SCALE_C 0.125f
#define LN_EPS  1e-5f

// Scratch (device globals — no dynamic allocation allowed). All fp16.
__device__ __half g_xn[(size_t)MROWS * DIM_N];
__device__ __half g_qkv[(size_t)MROWS * QKVD];
__device__ __half g_att[(size_t)MROWS * DIM_N];
__device__ __half g_wq[(size_t)QKVD * DIM_N];
__device__ __half g_wp[(size_t)DIM_N * DIM_N];

// ---------------------------------------------------------------------------
// PTX helpers
// ---------------------------------------------------------------------------
__device__ __forceinline__ uint32_t sptr(const void* p) {
    return (uint32_t)__cvta_generic_to_shared(p);
}
__device__ __forceinline__ void ldmx4(uint32_t* r, uint32_t a) {
    asm volatile("ldmatrix.sync.aligned.m8n8.x4.shared.b16 {%0,%1,%2,%3}, [%4];"
                 : "=r"(r[0]), "=r"(r[1]), "=r"(r[2]), "=r"(r[3]) : "r"(a));
}
__device__ __forceinline__ void ldmx4t(uint32_t* r, uint32_t a) {
    asm volatile("ldmatrix.sync.aligned.m8n8.x4.trans.shared.b16 {%0,%1,%2,%3}, [%4];"
                 : "=r"(r[0]), "=r"(r[1]), "=r"(r[2]), "=r"(r[3]) : "r"(a));
}
__device__ __forceinline__ void mma16816(float* c, const uint32_t* a,
                                         uint32_t b0, uint32_t b1) {
    asm volatile(
        "mma.sync.aligned.m16n8k16.row.col.f32.f16.f16.f32 "
        "{%0,%1,%2,%3}, {%4,%5,%6,%7}, {%8,%9}, {%0,%1,%2,%3};"
        : "+f"(c[0]), "+f"(c[1]), "+f"(c[2]), "+f"(c[3])
        : "r"(a[0]), "r"(a[1]), "r"(a[2]), "r"(a[3]), "r"(b0), "r"(b1));
}
__device__ __forceinline__ uint32_t packh2(float x, float y) {
    __half2 h = __floats2half2_rn(x, y);
    return *(uint32_t*)&h;
}
#define CP_ASYNC(dst, src) \
    asm volatile("cp.async.cg.shared.global [%0], [%1], 16;" :: "r"(dst), "l"(src))
#define CP_COMMIT() asm volatile("cp.async.commit_group;")
#define CP_WAITN(n) asm volatile("cp.async.wait_group %0;" :: "n"(n))

// ---------------------------------------------------------------------------
// Kernel 0: fp32 -> fp16 weight conversion
// ---------------------------------------------------------------------------
__global__ void cvt_f2h(const float* __restrict__ s, __half* __restrict__ d,
                        int n) {
    int i = (blockIdx.x * 256 + threadIdx.x) * 4;
    if (i < n) {
        float4 v = *(const float4*)(s + i);
        *(__half2*)(d + i)     = __floats2half2_rn(v.x, v.y);
        *(__half2*)(d + i + 2) = __floats2half2_rn(v.z, v.w);
    }
}

// ---------------------------------------------------------------------------
// Kernel 1: LayerNorm -> fp16 output. One block per row. 256 threads.
// ---------------------------------------------------------------------------
__global__ void ln_kernel(const float* __restrict__ x,
                          const float* __restrict__ w,
                          const float* __restrict__ b) {
    int row = blockIdx.x;
    const float* xr = x + (size_t)row * DIM_N;
    int t = threadIdx.x;
    float v0 = xr[t], v1 = xr[t + 256], v2 = xr[t + 512];
    float s  = v0 + v1 + v2;
    float sq = v0 * v0 + v1 * v1 + v2 * v2;
    #pragma unroll
    for (int o = 16; o; o >>= 1) {
        s  += __shfl_xor_sync(0xffffffffu, s, o);
        sq += __shfl_xor_sync(0xffffffffu, sq, o);
    }
    __shared__ float ss[8], ssq[8];
    int wid = t >> 5, lid = t & 31;
    if (lid == 0) { ss[wid] = s; ssq[wid] = sq; }
    __syncthreads();
    if (wid == 0) {
        s = ss[lid & 7]; sq = ssq[lid & 7];
        #pragma unroll
        for (int o = 4; o; o >>= 1) {
            s  += __shfl_xor_sync(0xffffffffu, s, o);
            sq += __shfl_xor_sync(0xffffffffu, sq, o);
        }
        if (lid == 0) { ss[0] = s; ssq[0] = sq; }
    }
    __syncthreads();
    float mean = ss[0] * (1.0f / DIM_N);
    float var  = ssq[0] * (1.0f / DIM_N) - mean * mean;
    float rstd = rsqrtf(var + LN_EPS);
    __half* o = g_xn + (size_t)row * DIM_N;
    int c = t;
    o[c] = __float2half((v0 - mean) * rstd * w[c] + b[c]); c += 256;
    o[c] = __float2half((v1 - mean) * rstd * w[c] + b[c]); c += 256;
    o[c] = __float2half((v2 - mean) * rstd * w[c] + b[c]);
}

// ---------------------------------------------------------------------------
// Kernel 2/4: fp16 HMMA GEMM  C[M,J] = A[M,K] @ W[J,K]^T + bias[J]
// 128x128 block tile, BK=64, 4 warps, warp tile 64x64 (4 MMA per ldmatrix),
// 3-stage cp.async ring, XOR-swizzled smem.
// ---------------------------------------------------------------------------
#define G_STGB 32768   // bytes per stage: A 16KB + B 16KB
#define G_SMEM (3 * G_STGB)

template <int OUT_HALF>
__global__ void __launch_bounds__(128)
hgemm_bias(const __half* __restrict__ A, const __half* __restrict__ W,
           const float* __restrict__ bias, void* __restrict__ Cv,
           int M, int J, int K) {
    extern __shared__ __align__(1024) char smg[];
    uint32_t sb = sptr(smg);

    int m0 = blockIdx.y * 128, j0 = blockIdx.x * 128;
    int tid = threadIdx.x, warp = tid >> 5, lane = tid & 31;
    int gid = lane >> 2, tig = lane & 3;
    int wm = (warp & 1) * 64, wn = (warp >> 1) * 64;

    // Fill addressing: thread = one row (128 rows), 8x16B units each
    int fr = tid;
    const __half* Ag = A + (size_t)(m0 + fr) * K;
    const __half* Wg = W + (size_t)(j0 + fr) * K;
    uint32_t rowb = fr * 128;
    uint32_t sw[8];
    #pragma unroll
    for (int u = 0; u < 8; u++) sw[u] = rowb + ((u ^ (fr & 7)) * 16);

    auto fill = [&](int c, int s) {
        uint32_t as = sb + s * G_STGB;
        uint32_t bs = as + 16384;
        #pragma unroll
        for (int u = 0; u < 8; u++) {
            CP_ASYNC(as + sw[u], Ag + c * 64 + u * 8);
            CP_ASYNC(bs + sw[u], Wg + c * 64 + u * 8);
        }
        CP_COMMIT();
    };

    int tile = lane >> 3, rlow = lane & 7;
    int rowin = (tile & 1) * 8 + rlow;
    int chsel = tile >> 1;

    float acc[4][8][4];
    #pragma unroll
    for (int mt = 0; mt < 4; mt++)
        #pragma unroll
        for (int nt = 0; nt < 8; nt++)
            #pragma unroll
            for (int e = 0; e < 4; e++) acc[mt][nt][e] = 0.0f;

    int nk = K / 64;                 // 12
    fill(0, 0); fill(1, 1); fill(2, 2);

    for (int i = 0; i < nk; i++) {
        int s = i - (i / 3) * 3;     // i % 3
        if (i + 2 < nk)      { CP_WAITN(2); }
        else if (i + 1 < nk) { CP_WAITN(1); }
        else                 { CP_WAITN(0); }
        __syncthreads();

        uint32_t Ab = sb + s * G_STGB, Bb = Ab + 16384;
        #pragma unroll
        for (int ks = 0; ks < 4; ks++) {
            int chunk = ((2 * ks + chsel) ^ rlow) * 8;
            uint32_t af[4][4];
            #pragma unroll
            for (int mt = 0; mt < 4; mt++)
                ldmx4(af[mt], Ab + ((wm + mt * 16 + rowin) * 64 + chunk) * 2);
            #pragma unroll
            for (int g = 0; g < 4; g++) {
                uint32_t r4[4];
                ldmx4(r4, Bb + ((wn + g * 16 + rowin) * 64 + chunk) * 2);
                #pragma unroll
                for (int mt = 0; mt < 4; mt++) {
                    mma16816(acc[mt][2 * g],     af[mt], r4[0], r4[2]);
                    mma16816(acc[mt][2 * g + 1], af[mt], r4[1], r4[3]);
                }
            }
        }
        __syncthreads();
        if (i + 3 < nk) fill(i + 3, s);
    }

    // Epilogue
    #pragma unroll
    for (int mt = 0; mt < 4; mt++) {
        int row0 = m0 + wm + mt * 16 + gid;
        #pragma unroll
        for (int nt = 0; nt < 8; nt++) {
            int col = j0 + wn + nt * 8 + tig * 2;
            float b0 = bias[col], b1 = bias[col + 1];
            if (OUT_HALF) {
                __half* C = (__half*)Cv;
                *(uint32_t*)&C[(size_t)row0 * J + col] =
                    packh2(acc[mt][nt][0] + b0, acc[mt][nt][1] + b1);
                *(uint32_t*)&C[(size_t)(row0 + 8) * J + col] =
                    packh2(acc[mt][nt][2] + b0, acc[mt][nt][3] + b1);
            } else {
                float* C = (float*)Cv;
                *(float2*)&C[(size_t)row0 * J + col] =
                    make_float2(acc[mt][nt][0] + b0, acc[mt][nt][1] + b1);
                *(float2*)&C[(size_t)(row0 + 8) * J + col] =
                    make_float2(acc[mt][nt][2] + b0, acc[mt][nt][3] + b1);
            }
        }
    }
}

// ---------------------------------------------------------------------------
// Kernel 3: fused flash attention, fp16 MMA (m16n8k16) — as in R4.
// ---------------------------------------------------------------------------
__global__ void __launch_bounds__(256, 2)
attn_kernel(const float* __restrict__ biases) {
    __shared__ __half Qs[128 * 64];
    __shared__ __half Ks[64 * 64];
    __shared__ __half Vs[64 * 64];
    __shared__ float  b_s[1024];

    int qt = blockIdx.x, h = blockIdx.y, b = blockIdx.z;
    int tid = threadIdx.x, warp = tid >> 5, lane = tid & 31;
    int gid = lane >> 2, tig = lane & 3;
    int n0 = qt * 128;

    for (int i = tid; i < 1024; i += 256) b_s[i] = biases[h * 1024 + i];

    {
        int r = tid >> 1, side = tid & 1;
        const __half* qp = g_qkv + (size_t)(b * N_TOK + n0 + r) * QKVD
                           + h * 192 + side * 32;
        #pragma unroll
        for (int j = 0; j < 4; j++) {
            int c = side * 4 + j;
            *(uint4*)&Qs[r * 64 + ((c ^ (r & 7)) * 8)] =
                *(const uint4*)(qp + 8 * j);
        }
    }

    int tile = lane >> 3, rlow = lane & 7;
    int rowin = (tile & 1) * 8 + rlow;
    int chsel = tile >> 1;
    uint32_t Qb = sptr(Qs), Kb = sptr(Ks), Vb = sptr(Vs);

    float oacc[8][4];
    #pragma unroll
    for (int nt = 0; nt < 8; nt++)
        #pragma unroll
        for (int e = 0; e < 4; e++) oacc[nt][e] = 0.0f;
    float m0r = -1e30f, m1r = -1e30f, l0r = 0.0f, l1r = 0.0f;

    int q0 = n0 + warp * 16 + gid, q1 = q0 + 8;
    int yq0 = q0 >> 5, xq0 = q0 & 31;
    int yq1 = q1 >> 5, xq1 = q1 & 31;

    for (int kt = 0; kt < 16; kt++) {
        {
            int r = tid >> 2, q = tid & 3;
            const __half* kp = g_qkv + (size_t)(b * N_TOK + kt * 64 + r) * QKVD
                               + h * 192 + 64 + q * 16;
            const __half* vp = kp + 64;
            #pragma unroll
            for (int j = 0; j < 2; j++) {
                int c = q * 2 + j;
                int off = r * 64 + ((c ^ (r & 7)) * 8);
                *(uint4*)&Ks[off] = *(const uint4*)(kp + 8 * j);
                *(uint4*)&Vs[off] = *(const uint4*)(vp + 8 * j);
            }
        }
        __syncthreads();

        float sacc[8][4];
        #pragma unroll
        for (int nt = 0; nt < 8; nt++)
            #pragma unroll
            for (int e = 0; e < 4; e++) sacc[nt][e] = 0.0f;
        #pragma unroll
        for (int ks = 0; ks < 4; ks++) {
            int chunk = ((2 * ks + chsel) ^ rlow) * 8;
            uint32_t af[4];
            ldmx4(af, Qb + ((warp * 16 + rowin) * 64 + chunk) * 2);
            #pragma unroll
            for (int g = 0; g < 4; g++) {
                uint32_t r4[4];
                ldmx4(r4, Kb + ((g * 16 + rowin) * 64 + chunk) * 2);
                mma16816(sacc[2 * g],     af, r4[0], r4[2]);
                mma16816(sacc[2 * g + 1], af, r4[1], r4[3]);
            }
        }

        float px0 = -1e30f, px1 = -1e30f;
        #pragma unroll
        for (int nt = 0; nt < 8; nt++) {
            #pragma unroll
            for (int e = 0; e < 2; e++) {
                int key = kt * 64 + nt * 8 + tig * 2 + e;
                int ym = key >> 5, xm = key & 31;
                float bv0 = b_s[abs(yq0 - ym) * 32 + abs(xq0 - xm)];
                float bv1 = b_s[abs(yq1 - ym) * 32 + abs(xq1 - xm)];
                sacc[nt][e]     = sacc[nt][e]     * SCALE_C + bv0;
                sacc[nt][e + 2] = sacc[nt][e + 2] * SCALE_C + bv1;
                px0 = fmaxf(px0, sacc[nt][e]);
                px1 = fmaxf(px1, sacc[nt][e + 2]);
            }
        }
        px0 = fmaxf(px0, __shfl_xor_sync(0xffffffffu, px0, 1));
        px0 = fmaxf(px0, __shfl_xor_sync(0xffffffffu, px0, 2));
        px1 = fmaxf(px1, __shfl_xor_sync(0xffffffffu, px1, 1));
        px1 = fmaxf(px1, __shfl_xor_sync(0xffffffffu, px1, 2));

        float mn0 = fmaxf(m0r, px0), mn1 = fmaxf(m1r, px1);
        float cr0 = __expf(m0r - mn0), cr1 = __expf(m1r - mn1);
        float s0 = 0.0f, s1 = 0.0f;
        #pragma unroll
        for (int nt = 0; nt < 8; nt++) {
            #pragma unroll
            for (int e = 0; e < 2; e++) {
                float p0 = __expf(sacc[nt][e] - mn0);
                float p1 = __expf(sacc[nt][e + 2] - mn1);
                s0 += p0; s1 += p1;
                sacc[nt][e] = p0; sacc[nt][e + 2] = p1;
            }
        }
        s0 += __shfl_xor_sync(0xffffffffu, s0, 1);
        s0 += __shfl_xor_sync(0xffffffffu, s0, 2);
        s1 += __shfl_xor_sync(0xffffffffu, s1, 1);
        s1 += __shfl_xor_sync(0xffffffffu, s1, 2);
        l0r = l0r * cr0 + s0; m0r = mn0;
        l1r = l1r * cr1 + s1; m1r = mn1;
        #pragma unroll
        for (int nt = 0; nt < 8; nt++) {
            oacc[nt][0] *= cr0; oacc[nt][1] *= cr0;
            oacc[nt][2] *= cr1; oacc[nt][3] *= cr1;
        }

        #pragma unroll
        for (int c = 0; c < 4; c++) {
            uint32_t pa[4];
            pa[0] = packh2(sacc[2 * c][0],     sacc[2 * c][1]);
            pa[1] = packh2(sacc[2 * c][2],     sacc[2 * c][3]);
            pa[2] = packh2(sacc[2 * c + 1][0], sacc[2 * c + 1][1]);
            pa[3] = packh2(sacc[2 * c + 1][2], sacc[2 * c + 1][3]);
            #pragma unroll
            for (int g = 0; g < 4; g++) {
                uint32_t r4[4];
                int row = c * 16 + rowin;
                ldmx4t(r4, Vb + (row * 64 + (((2 * g + chsel) ^ (row & 7)) * 8)) * 2);
                mma16816(oacc[2 * g],     pa, r4[0], r4[1]);
                mma16816(oacc[2 * g + 1], pa, r4[2], r4[3]);
            }
        }
        __syncthreads();
    }

    float inv0 = 1.0f / l0r, inv1 = 1.0f / l1r;
    size_t row0 = (size_t)(b * N_TOK + n0 + warp * 16 + gid) * DIM_N;
    size_t row1 = row0 + 8 * DIM_N;
    #pragma unroll
    for (int nt = 0; nt < 8; nt++) {
        int col = h * 64 + nt * 8 + tig * 2;
        *(uint32_t*)&g_att[row0 + col] =
            packh2(oacc[nt][0] * inv0, oacc[nt][1] * inv0);
        *(uint32_t*)&g_att[row1 + col] =
            packh2(oacc[nt][2] * inv1, oacc[nt][3] * inv1);
    }
}

// ---------------------------------------------------------------------------
extern "C" void kernel_launch(void* const* d_in, const int* in_sizes, int n_in,
                              void* d_out, int out_size) {
    const float* x           = (const float*)d_in[0];
    const float* ln_w        = (const float*)d_in[1];
    const float* ln_b        = (const float*)d_in[2];
    const float* qkv_w       = (const float*)d_in[3];
    const float* qkv_b       = (const float*)d_in[4];
    const float* proj_w      = (const float*)d_in[5];
    const float* proj_b      = (const float*)d_in[6];
    const float* attn_biases = (const float*)d_in[7];

    void *p_xn, *p_qkv, *p_att, *p_wq, *p_wp;
    cudaGetSymbolAddress(&p_xn, g_xn);
    cudaGetSymbolAddress(&p_qkv, g_qkv);
    cudaGetSymbolAddress(&p_att, g_att);
    cudaGetSymbolAddress(&p_wq, g_wq);
    cudaGetSymbolAddress(&p_wp, g_wp);

    cudaFuncSetAttribute(hgemm_bias<1>,
                         cudaFuncAttributeMaxDynamicSharedMemorySize, G_SMEM);
    cudaFuncSetAttribute(hgemm_bias<0>,
                         cudaFuncAttributeMaxDynamicSharedMemorySize, G_SMEM);

    // 0. Weight conversion fp32 -> fp16
    cvt_f2h<<<(QKVD * DIM_N / 4 + 255) / 256, 256>>>(qkv_w, (__half*)p_wq,
                                                     QKVD * DIM_N);
    cvt_f2h<<<(DIM_N * DIM_N / 4 + 255) / 256, 256>>>(proj_w, (__half*)p_wp,
                                                      DIM_N * DIM_N);

    // 1. LayerNorm -> fp16
    ln_kernel<<<MROWS, 256>>>(x, ln_w, ln_b);

    // 2. QKV GEMM (fp16 HMMA, 64x64 warp tile): [16384,768] @ [2304,768]^T
    hgemm_bias<1><<<dim3(QKVD / 128, MROWS / 128), 128, G_SMEM>>>(
        (const __half*)p_xn, (const __half*)p_wq, qkv_b, p_qkv,
        MROWS, QKVD, DIM_N);

    // 3. Fused attention (fp16 HMMA)
    attn_kernel<<<dim3(N_TOK / 128, H_N, B_N), 256>>>(attn_biases);

    // 4. Projection GEMM (fp16 HMMA) -> fp32 output
    hgemm_bias<0><<<dim3(DIM_N / 128, MROWS / 128), 128, G_SMEM>>>(
        (const __half*)p_att, (const __half*)p_wp, proj_b, d_out,
        MROWS, DIM_N, DIM_N);
}

// round 7
// speedup vs baseline: 1.2887x; 1.2887x over previous
#include <cuda_runtime.h>
#include <cuda_fp16.h>
#include <math.h>
#include <stdint.h>

// Problem constants
#define B_N   16
#define N_TOK 1024
#define DIM_N 768
#define H_N   12
#define QKVD  2304
#define MROWS 16384
#define SCALE_C 0.125f
#define LN_EPS  1e-5f

// Scratch (device globals — no dynamic allocation allowed). All fp16.
__device__ __half g_xn[(size_t)MROWS * DIM_N];
__device__ __half g_qkv[(size_t)MROWS * QKVD];
__device__ __half g_att[(size_t)MROWS * DIM_N];
__device__ __half g_wq[(size_t)QKVD * DIM_N];
__device__ __half g_wp[(size_t)DIM_N * DIM_N];

// ---------------------------------------------------------------------------
// PTX helpers
// ---------------------------------------------------------------------------
__device__ __forceinline__ uint32_t sptr(const void* p) {
    return (uint32_t)__cvta_generic_to_shared(p);
}
__device__ __forceinline__ void ldmx4(uint32_t* r, uint32_t a) {
    asm volatile("ldmatrix.sync.aligned.m8n8.x4.shared.b16 {%0,%1,%2,%3}, [%4];"
                 : "=r"(r[0]), "=r"(r[1]), "=r"(r[2]), "=r"(r[3]) : "r"(a));
}
__device__ __forceinline__ void ldmx4t(uint32_t* r, uint32_t a) {
    asm volatile("ldmatrix.sync.aligned.m8n8.x4.trans.shared.b16 {%0,%1,%2,%3}, [%4];"
                 : "=r"(r[0]), "=r"(r[1]), "=r"(r[2]), "=r"(r[3]) : "r"(a));
}
__device__ __forceinline__ void mma16816(float* c, const uint32_t* a,
                                         uint32_t b0, uint32_t b1) {
    asm volatile(
        "mma.sync.aligned.m16n8k16.row.col.f32.f16.f16.f32 "
        "{%0,%1,%2,%3}, {%4,%5,%6,%7}, {%8,%9}, {%0,%1,%2,%3};"
        : "+f"(c[0]), "+f"(c[1]), "+f"(c[2]), "+f"(c[3])
        : "r"(a[0]), "r"(a[1]), "r"(a[2]), "r"(a[3]), "r"(b0), "r"(b1));
}
__device__ __forceinline__ uint32_t packh2(float x, float y) {
    __half2 h = __floats2half2_rn(x, y);
    return *(uint32_t*)&h;
}
#define CP_ASYNC(dst, src) \
    asm volatile("cp.async.cg.shared.global [%0], [%1], 16;" :: "r"(dst), "l"(src))
#define CP_COMMIT() asm volatile("cp.async.commit_group;")
#define CP_WAITN(n) asm volatile("cp.async.wait_group %0;" :: "n"(n))

// ---------------------------------------------------------------------------
// Kernel 0: fp32 -> fp16 weight conversion
// ---------------------------------------------------------------------------
__global__ void cvt_f2h(const float* __restrict__ s, __half* __restrict__ d,
                        int n) {
    int i = (blockIdx.x * 256 + threadIdx.x) * 4;
    if (i < n) {
        float4 v = *(const float4*)(s + i);
        *(__half2*)(d + i)     = __floats2half2_rn(v.x, v.y);
        *(__half2*)(d + i + 2) = __floats2half2_rn(v.z, v.w);
    }
}

// ---------------------------------------------------------------------------
// Kernel 1: LayerNorm -> fp16 output. One block per row. 256 threads.
// ---------------------------------------------------------------------------
__global__ void ln_kernel(const float* __restrict__ x,
                          const float* __restrict__ w,
                          const float* __restrict__ b) {
    int row = blockIdx.x;
    const float* xr = x + (size_t)row * DIM_N;
    int t = threadIdx.x;
    float v0 = xr[t], v1 = xr[t + 256], v2 = xr[t + 512];
    float s  = v0 + v1 + v2;
    float sq = v0 * v0 + v1 * v1 + v2 * v2;
    #pragma unroll
    for (int o = 16; o; o >>= 1) {
        s  += __shfl_xor_sync(0xffffffffu, s, o);
        sq += __shfl_xor_sync(0xffffffffu, sq, o);
    }
    __shared__ float ss[8], ssq[8];
    int wid = t >> 5, lid = t & 31;
    if (lid == 0) { ss[wid] = s; ssq[wid] = sq; }
    __syncthreads();
    if (wid == 0) {
        s = ss[lid & 7]; sq = ssq[lid & 7];
        #pragma unroll
        for (int o = 4; o; o >>= 1) {
            s  += __shfl_xor_sync(0xffffffffu, s, o);
            sq += __shfl_xor_sync(0xffffffffu, sq, o);
        }
        if (lid == 0) { ss[0] = s; ssq[0] = sq; }
    }
    __syncthreads();
    float mean = ss[0] * (1.0f / DIM_N);
    float var  = ssq[0] * (1.0f / DIM_N) - mean * mean;
    float rstd = rsqrtf(var + LN_EPS);
    __half* o = g_xn + (size_t)row * DIM_N;
    int c = t;
    o[c] = __float2half((v0 - mean) * rstd * w[c] + b[c]); c += 256;
    o[c] = __float2half((v1 - mean) * rstd * w[c] + b[c]); c += 256;
    o[c] = __float2half((v2 - mean) * rstd * w[c] + b[c]);
}

// ---------------------------------------------------------------------------
// Kernel 2/4: fp16 HMMA GEMM  C[M,J] = A[M,K] @ W[J,K]^T + bias[J]
// R4 shape: 128x128 tile, BK=64, 8 warps (2x4), warp 64x32, 115 regs,
// 2 CTAs/SM — now with a 3-stage cp.async ring.
// ---------------------------------------------------------------------------
#define G_STGB 32768            // per stage: A 16KB + B 16KB
#define G_SMEM (3 * G_STGB)     // 96 KB

template <int OUT_HALF>
__global__ void __launch_bounds__(256, 2)
hgemm_bias(const __half* __restrict__ A, const __half* __restrict__ W,
           const float* __restrict__ bias, void* __restrict__ Cv,
           int M, int J, int K) {
    extern __shared__ __align__(1024) char smg[];
    uint32_t sb = sptr(smg);

    int m0 = blockIdx.y * 128, j0 = blockIdx.x * 128;
    int tid = threadIdx.x, warp = tid >> 5, lane = tid & 31;
    int gid = lane >> 2, tig = lane & 3;
    int wm = (warp >> 2) * 64, wn = (warp & 3) * 32;
    int lr = tid >> 1, side = tid & 1;

    const __half* Ap = A + (size_t)(m0 + lr) * K + side * 32;
    const __half* Wp = W + (size_t)(j0 + lr) * K + side * 32;

    uint32_t sw[4];
    #pragma unroll
    for (int j = 0; j < 4; j++) {
        int c = side * 4 + j;
        sw[j] = (lr * 64 + ((c ^ (lr & 7)) * 8)) * 2;
    }

    auto fill = [&](int c, int s) {
        uint32_t as = sb + s * G_STGB;
        uint32_t bs = as + 16384;
        #pragma unroll
        for (int j = 0; j < 4; j++) {
            CP_ASYNC(as + sw[j], Ap + c * 64 + 8 * j);
            CP_ASYNC(bs + sw[j], Wp + c * 64 + 8 * j);
        }
        CP_COMMIT();
    };

    int tile = lane >> 3, rlow = lane & 7;
    int rowin = (tile & 1) * 8 + rlow;
    int chsel = tile >> 1;

    float acc[4][4][4];
    #pragma unroll
    for (int mt = 0; mt < 4; mt++)
        #pragma unroll
        for (int nt = 0; nt < 4; nt++)
            #pragma unroll
            for (int e = 0; e < 4; e++) acc[mt][nt][e] = 0.0f;

    int nk = K / 64;                 // 12
    fill(0, 0); fill(1, 1); fill(2, 2);

    for (int i = 0; i < nk; i++) {
        int s = i - (i / 3) * 3;
        if (i + 2 < nk)      { CP_WAITN(2); }
        else if (i + 1 < nk) { CP_WAITN(1); }
        else                 { CP_WAITN(0); }
        __syncthreads();

        uint32_t Ab = sb + s * G_STGB, Bb = Ab + 16384;
        #pragma unroll
        for (int ks = 0; ks < 4; ks++) {
            int chunk = ((2 * ks + chsel) ^ rlow) * 8;
            uint32_t af[4][4];
            #pragma unroll
            for (int mt = 0; mt < 4; mt++)
                ldmx4(af[mt], Ab + ((wm + mt * 16 + rowin) * 64 + chunk) * 2);
            #pragma unroll
            for (int g = 0; g < 2; g++) {
                uint32_t r4[4];
                ldmx4(r4, Bb + ((wn + g * 16 + rowin) * 64 + chunk) * 2);
                #pragma unroll
                for (int mt = 0; mt < 4; mt++) {
                    mma16816(acc[mt][2 * g],     af[mt], r4[0], r4[2]);
                    mma16816(acc[mt][2 * g + 1], af[mt], r4[1], r4[3]);
                }
            }
        }
        __syncthreads();
        if (i + 3 < nk) fill(i + 3, s);
    }

    // Epilogue
    #pragma unroll
    for (int mt = 0; mt < 4; mt++) {
        int row0 = m0 + wm + mt * 16 + gid;
        #pragma unroll
        for (int nt = 0; nt < 4; nt++) {
            int col = j0 + wn + nt * 8 + tig * 2;
            float b0 = bias[col], b1 = bias[col + 1];
            if (OUT_HALF) {
                __half* C = (__half*)Cv;
                *(uint32_t*)&C[(size_t)row0 * J + col] =
                    packh2(acc[mt][nt][0] + b0, acc[mt][nt][1] + b1);
                *(uint32_t*)&C[(size_t)(row0 + 8) * J + col] =
                    packh2(acc[mt][nt][2] + b0, acc[mt][nt][3] + b1);
            } else {
                float* C = (float*)Cv;
                *(float2*)&C[(size_t)row0 * J + col] =
                    make_float2(acc[mt][nt][0] + b0, acc[mt][nt][1] + b1);
                *(float2*)&C[(size_t)(row0 + 8) * J + col] =
                    make_float2(acc[mt][nt][2] + b0, acc[mt][nt][3] + b1);
            }
        }
    }
}

// ---------------------------------------------------------------------------
// Kernel 3: fused flash attention, fp16 MMA — now with cp.async
// double-buffered K/V tiles. Dynamic smem:
//   Q[128*64]h | K[2][64*64]h | V[2][64*64]h | bias[1024]f  = 53248 B
// ---------------------------------------------------------------------------
#define ATTN_SMEM 53248

__global__ void __launch_bounds__(256, 2)
attn_kernel(const float* __restrict__ biases) {
    extern __shared__ __align__(1024) char sma[];
    __half* Qh = (__half*)sma;
    float*  b_s = (float*)(sma + 49152);
    uint32_t Qb = sptr(sma);
    uint32_t Kb = Qb + 16384;   // 2 stages of 8192 B
    uint32_t Vb = Qb + 32768;   // 2 stages of 8192 B

    int qt = blockIdx.x, h = blockIdx.y, b = blockIdx.z;
    int tid = threadIdx.x, warp = tid >> 5, lane = tid & 31;
    int gid = lane >> 2, tig = lane & 3;
    int n0 = qt * 128;

    for (int i = tid; i < 1024; i += 256) b_s[i] = biases[h * 1024 + i];

    // Stage Q [128 rows][64 dims], swizzled
    {
        int r = tid >> 1, side = tid & 1;
        const __half* qp = g_qkv + (size_t)(b * N_TOK + n0 + r) * QKVD
                           + h * 192 + side * 32;
        #pragma unroll
        for (int j = 0; j < 4; j++) {
            int c = side * 4 + j;
            *(uint4*)&Qh[r * 64 + ((c ^ (r & 7)) * 8)] =
                *(const uint4*)(qp + 8 * j);
        }
    }

    // K/V fill via cp.async
    int fr = tid >> 2, fq = tid & 3;
    uint32_t fsw[2];
    #pragma unroll
    for (int j = 0; j < 2; j++) {
        int c = fq * 2 + j;
        fsw[j] = (fr * 64 + ((c ^ (fr & 7)) * 8)) * 2;
    }
    auto fillkv = [&](int kt, int s) {
        const __half* kp = g_qkv + (size_t)(b * N_TOK + kt * 64 + fr) * QKVD
                           + h * 192 + 64 + fq * 16;
        const __half* vp = kp + 64;
        #pragma unroll
        for (int j = 0; j < 2; j++) {
            CP_ASYNC(Kb + s * 8192 + fsw[j], kp + 8 * j);
            CP_ASYNC(Vb + s * 8192 + fsw[j], vp + 8 * j);
        }
        CP_COMMIT();
    };

    int tile = lane >> 3, rlow = lane & 7;
    int rowin = (tile & 1) * 8 + rlow;
    int chsel = tile >> 1;

    float oacc[8][4];
    #pragma unroll
    for (int nt = 0; nt < 8; nt++)
        #pragma unroll
        for (int e = 0; e < 4; e++) oacc[nt][e] = 0.0f;
    float m0r = -1e30f, m1r = -1e30f, l0r = 0.0f, l1r = 0.0f;

    int q0 = n0 + warp * 16 + gid, q1 = q0 + 8;
    int yq0 = q0 >> 5, xq0 = q0 & 31;
    int yq1 = q1 >> 5, xq1 = q1 & 31;

    fillkv(0, 0);

    for (int kt = 0; kt < 16; kt++) {
        if (kt + 1 < 16) { fillkv(kt + 1, (kt + 1) & 1); CP_WAITN(1); }
        else             { CP_WAITN(0); }
        __syncthreads();

        uint32_t Kcur = Kb + (kt & 1) * 8192;
        uint32_t Vcur = Vb + (kt & 1) * 8192;

        // S = Q @ K^T
        float sacc[8][4];
        #pragma unroll
        for (int nt = 0; nt < 8; nt++)
            #pragma unroll
            for (int e = 0; e < 4; e++) sacc[nt][e] = 0.0f;
        #pragma unroll
        for (int ks = 0; ks < 4; ks++) {
            int chunk = ((2 * ks + chsel) ^ rlow) * 8;
            uint32_t af[4];
            ldmx4(af, Qb + ((warp * 16 + rowin) * 64 + chunk) * 2);
            #pragma unroll
            for (int g = 0; g < 4; g++) {
                uint32_t r4[4];
                ldmx4(r4, Kcur + ((g * 16 + rowin) * 64 + chunk) * 2);
                mma16816(sacc[2 * g],     af, r4[0], r4[2]);
                mma16816(sacc[2 * g + 1], af, r4[1], r4[3]);
            }
        }

        // scale + analytic relative-position bias; online softmax
        float px0 = -1e30f, px1 = -1e30f;
        #pragma unroll
        for (int nt = 0; nt < 8; nt++) {
            #pragma unroll
            for (int e = 0; e < 2; e++) {
                int key = kt * 64 + nt * 8 + tig * 2 + e;
                int ym = key >> 5, xm = key & 31;
                float bv0 = b_s[abs(yq0 - ym) * 32 + abs(xq0 - xm)];
                float bv1 = b_s[abs(yq1 - ym) * 32 + abs(xq1 - xm)];
                sacc[nt][e]     = sacc[nt][e]     * SCALE_C + bv0;
                sacc[nt][e + 2] = sacc[nt][e + 2] * SCALE_C + bv1;
                px0 = fmaxf(px0, sacc[nt][e]);
                px1 = fmaxf(px1, sacc[nt][e + 2]);
            }
        }
        px0 = fmaxf(px0, __shfl_xor_sync(0xffffffffu, px0, 1));
        px0 = fmaxf(px0, __shfl_xor_sync(0xffffffffu, px0, 2));
        px1 = fmaxf(px1, __shfl_xor_sync(0xffffffffu, px1, 1));
        px1 = fmaxf(px1, __shfl_xor_sync(0xffffffffu, px1, 2));

        float mn0 = fmaxf(m0r, px0), mn1 = fmaxf(m1r, px1);
        float cr0 = __expf(m0r - mn0), cr1 = __expf(m1r - mn1);
        float s0 = 0.0f, s1 = 0.0f;
        #pragma unroll
        for (int nt = 0; nt < 8; nt++) {
            #pragma unroll
            for (int e = 0; e < 2; e++) {
                float p0 = __expf(sacc[nt][e] - mn0);
                float p1 = __expf(sacc[nt][e + 2] - mn1);
                s0 += p0; s1 += p1;
                sacc[nt][e] = p0; sacc[nt][e + 2] = p1;
            }
        }
        s0 += __shfl_xor_sync(0xffffffffu, s0, 1);
        s0 += __shfl_xor_sync(0xffffffffu, s0, 2);
        s1 += __shfl_xor_sync(0xffffffffu, s1, 1);
        s1 += __shfl_xor_sync(0xffffffffu, s1, 2);
        l0r = l0r * cr0 + s0; m0r = mn0;
        l1r = l1r * cr1 + s1; m1r = mn1;
        #pragma unroll
        for (int nt = 0; nt < 8; nt++) {
            oacc[nt][0] *= cr0; oacc[nt][1] *= cr0;
            oacc[nt][2] *= cr1; oacc[nt][3] *= cr1;
        }

        // O += P @ V, P repacked in registers
        #pragma unroll
        for (int c = 0; c < 4; c++) {
            uint32_t pa[4];
            pa[0] = packh2(sacc[2 * c][0],     sacc[2 * c][1]);
            pa[1] = packh2(sacc[2 * c][2],     sacc[2 * c][3]);
            pa[2] = packh2(sacc[2 * c + 1][0], sacc[2 * c + 1][1]);
            pa[3] = packh2(sacc[2 * c + 1][2], sacc[2 * c + 1][3]);
            #pragma unroll
            for (int g = 0; g < 4; g++) {
                uint32_t r4[4];
                int row = c * 16 + rowin;
                ldmx4t(r4, Vcur + (row * 64 + (((2 * g + chsel) ^ (row & 7)) * 8)) * 2);
                mma16816(oacc[2 * g],     pa, r4[0], r4[1]);
                mma16816(oacc[2 * g + 1], pa, r4[2], r4[3]);
            }
        }
        __syncthreads();
    }

    float inv0 = 1.0f / l0r, inv1 = 1.0f / l1r;
    size_t row0 = (size_t)(b * N_TOK + n0 + warp * 16 + gid) * DIM_N;
    size_t row1 = row0 + 8 * DIM_N;
    #pragma unroll
    for (int nt = 0; nt < 8; nt++) {
        int col = h * 64 + nt * 8 + tig * 2;
        *(uint32_t*)&g_att[row0 + col] =
            packh2(oacc[nt][0] * inv0, oacc[nt][1] * inv0);
        *(uint32_t*)&g_att[row1 + col] =
            packh2(oacc[nt][2] * inv1, oacc[nt][3] * inv1);
    }
}

// ---------------------------------------------------------------------------
extern "C" void kernel_launch(void* const* d_in, const int* in_sizes, int n_in,
                              void* d_out, int out_size) {
    const float* x           = (const float*)d_in[0];
    const float* ln_w        = (const float*)d_in[1];
    const float* ln_b        = (const float*)d_in[2];
    const float* qkv_w       = (const float*)d_in[3];
    const float* qkv_b       = (const float*)d_in[4];
    const float* proj_w      = (const float*)d_in[5];
    const float* proj_b      = (const float*)d_in[6];
    const float* attn_biases = (const float*)d_in[7];

    void *p_xn, *p_qkv, *p_att, *p_wq, *p_wp;
    cudaGetSymbolAddress(&p_xn, g_xn);
    cudaGetSymbolAddress(&p_qkv, g_qkv);
    cudaGetSymbolAddress(&p_att, g_att);
    cudaGetSymbolAddress(&p_wq, g_wq);
    cudaGetSymbolAddress(&p_wp, g_wp);

    cudaFuncSetAttribute(hgemm_bias<1>,
                         cudaFuncAttributeMaxDynamicSharedMemorySize, G_SMEM);
    cudaFuncSetAttribute(hgemm_bias<0>,
                         cudaFuncAttributeMaxDynamicSharedMemorySize, G_SMEM);
    cudaFuncSetAttribute(attn_kernel,
                         cudaFuncAttributeMaxDynamicSharedMemorySize, ATTN_SMEM);

    // 0. Weight conversion fp32 -> fp16
    cvt_f2h<<<(QKVD * DIM_N / 4 + 255) / 256, 256>>>(qkv_w, (__half*)p_wq,
                                                     QKVD * DIM_N);
    cvt_f2h<<<(DIM_N * DIM_N / 4 + 255) / 256, 256>>>(proj_w, (__half*)p_wp,
                                                      DIM_N * DIM_N);

    // 1. LayerNorm -> fp16
    ln_kernel<<<MROWS, 256>>>(x, ln_w, ln_b);

    // 2. QKV GEMM (fp16 HMMA): [16384,768] @ [2304,768]^T
    hgemm_bias<1><<<dim3(QKVD / 128, MROWS / 128), 256, G_SMEM>>>(
        (const __half*)p_xn, (const __half*)p_wq, qkv_b, p_qkv,
        MROWS, QKVD, DIM_N);

    // 3. Fused attention (fp16 HMMA, cp.async K/V pipeline)
    attn_kernel<<<dim3(N_TOK / 128, H_N, B_N), 256, ATTN_SMEM>>>(attn_biases);

    // 4. Projection GEMM (fp16 HMMA) -> fp32 output
    hgemm_bias<0><<<dim3(DIM_N / 128, MROWS / 128), 256, G_SMEM>>>(
        (const __half*)p_att, (const __half*)p_wp, proj_b, d_out,
        MROWS, DIM_N, DIM_N);
}

// round 8
// speedup vs baseline: 1.3180x; 1.0228x over previous
#include <cuda_runtime.h>
#include <cuda_fp16.h>
#include <math.h>
#include <stdint.h>

// Problem constants
#define B_N   16
#define N_TOK 1024
#define DIM_N 768
#define H_N   12
#define QKVD  2304
#define MROWS 16384
#define SCALE_C 0.125f
#define LOG2E 1.4426950408889634f
#define LN_EPS  1e-5f

// Scratch (device globals — no dynamic allocation allowed). All fp16.
__device__ __half g_xn[(size_t)MROWS * DIM_N];
__device__ __half g_qkv[(size_t)MROWS * QKVD];
__device__ __half g_att[(size_t)MROWS * DIM_N];
__device__ __half g_wq[(size_t)QKVD * DIM_N];
__device__ __half g_wp[(size_t)DIM_N * DIM_N];

// ---------------------------------------------------------------------------
// PTX helpers
// ---------------------------------------------------------------------------
__device__ __forceinline__ uint32_t sptr(const void* p) {
    return (uint32_t)__cvta_generic_to_shared(p);
}
__device__ __forceinline__ void ldmx4(uint32_t* r, uint32_t a) {
    asm volatile("ldmatrix.sync.aligned.m8n8.x4.shared.b16 {%0,%1,%2,%3}, [%4];"
                 : "=r"(r[0]), "=r"(r[1]), "=r"(r[2]), "=r"(r[3]) : "r"(a));
}
__device__ __forceinline__ void ldmx4t(uint32_t* r, uint32_t a) {
    asm volatile("ldmatrix.sync.aligned.m8n8.x4.trans.shared.b16 {%0,%1,%2,%3}, [%4];"
                 : "=r"(r[0]), "=r"(r[1]), "=r"(r[2]), "=r"(r[3]) : "r"(a));
}
__device__ __forceinline__ void mma16816(float* c, const uint32_t* a,
                                         uint32_t b0, uint32_t b1) {
    asm volatile(
        "mma.sync.aligned.m16n8k16.row.col.f32.f16.f16.f32 "
        "{%0,%1,%2,%3}, {%4,%5,%6,%7}, {%8,%9}, {%0,%1,%2,%3};"
        : "+f"(c[0]), "+f"(c[1]), "+f"(c[2]), "+f"(c[3])
        : "r"(a[0]), "r"(a[1]), "r"(a[2]), "r"(a[3]), "r"(b0), "r"(b1));
}
__device__ __forceinline__ uint32_t packh2(float x, float y) {
    __half2 h = __floats2half2_rn(x, y);
    return *(uint32_t*)&h;
}
__device__ __forceinline__ uint32_t ex2h2(uint32_t x) {
    uint32_t r;
    asm("ex2.approx.f16x2 %0, %1;" : "=r"(r) : "r"(x));
    return r;
}
__device__ __forceinline__ float ex2f(float x) {
    float r;
    asm("ex2.approx.f32 %0, %1;" : "=f"(r) : "f"(x));
    return r;
}
#define CP_ASYNC(dst, src) \
    asm volatile("cp.async.cg.shared.global [%0], [%1], 16;" :: "r"(dst), "l"(src))
#define CP_COMMIT() asm volatile("cp.async.commit_group;")
#define CP_WAITN(n) asm volatile("cp.async.wait_group %0;" :: "n"(n))

// ---------------------------------------------------------------------------
// Kernel 0: fp32 -> fp16 weight conversion
// ---------------------------------------------------------------------------
__global__ void cvt_f2h(const float* __restrict__ s, __half* __restrict__ d,
                        int n) {
    int i = (blockIdx.x * 256 + threadIdx.x) * 4;
    if (i < n) {
        float4 v = *(const float4*)(s + i);
        *(__half2*)(d + i)     = __floats2half2_rn(v.x, v.y);
        *(__half2*)(d + i + 2) = __floats2half2_rn(v.z, v.w);
    }
}

// ---------------------------------------------------------------------------
// Kernel 1: LayerNorm -> fp16 output. One block per row. 256 threads.
// ---------------------------------------------------------------------------
__global__ void ln_kernel(const float* __restrict__ x,
                          const float* __restrict__ w,
                          const float* __restrict__ b) {
    int row = blockIdx.x;
    const float* xr = x + (size_t)row * DIM_N;
    int t = threadIdx.x;
    float v0 = xr[t], v1 = xr[t + 256], v2 = xr[t + 512];
    float s  = v0 + v1 + v2;
    float sq = v0 * v0 + v1 * v1 + v2 * v2;
    #pragma unroll
    for (int o = 16; o; o >>= 1) {
        s  += __shfl_xor_sync(0xffffffffu, s, o);
        sq += __shfl_xor_sync(0xffffffffu, sq, o);
    }
    __shared__ float ss[8], ssq[8];
    int wid = t >> 5, lid = t & 31;
    if (lid == 0) { ss[wid] = s; ssq[wid] = sq; }
    __syncthreads();
    if (wid == 0) {
        s = ss[lid & 7]; sq = ssq[lid & 7];
        #pragma unroll
        for (int o = 4; o; o >>= 1) {
            s  += __shfl_xor_sync(0xffffffffu, s, o);
            sq += __shfl_xor_sync(0xffffffffu, sq, o);
        }
        if (lid == 0) { ss[0] = s; ssq[0] = sq; }
    }
    __syncthreads();
    float mean = ss[0] * (1.0f / DIM_N);
    float var  = ssq[0] * (1.0f / DIM_N) - mean * mean;
    float rstd = rsqrtf(var + LN_EPS);
    __half* o = g_xn + (size_t)row * DIM_N;
    int c = t;
    o[c] = __float2half((v0 - mean) * rstd * w[c] + b[c]); c += 256;
    o[c] = __float2half((v1 - mean) * rstd * w[c] + b[c]); c += 256;
    o[c] = __float2half((v2 - mean) * rstd * w[c] + b[c]);
}

// ---------------------------------------------------------------------------
// Kernel 2/4: fp16 HMMA GEMM  C[M,J] = A[M,K] @ W[J,K]^T + bias[J]
// 128x128 tile, BK=64, 8 warps (2x4), warp 64x32, 3-stage cp.async ring,
// ONE __syncthreads per chunk (fill-after-sync into the slot freed last iter).
// ---------------------------------------------------------------------------
#define G_STGB 32768            // per stage: A 16KB + B 16KB
#define G_SMEM (3 * G_STGB)     // 96 KB

template <int OUT_HALF>
__global__ void __launch_bounds__(256, 2)
hgemm_bias(const __half* __restrict__ A, const __half* __restrict__ W,
           const float* __restrict__ bias, void* __restrict__ Cv,
           int M, int J, int K) {
    extern __shared__ __align__(1024) char smg[];
    uint32_t sb = sptr(smg);

    int m0 = blockIdx.y * 128, j0 = blockIdx.x * 128;
    int tid = threadIdx.x, warp = tid >> 5, lane = tid & 31;
    int gid = lane >> 2, tig = lane & 3;
    int wm = (warp >> 2) * 64, wn = (warp & 3) * 32;
    int lr = tid >> 1, side = tid & 1;

    const __half* Ap = A + (size_t)(m0 + lr) * K + side * 32;
    const __half* Wp = W + (size_t)(j0 + lr) * K + side * 32;

    uint32_t sw[4];
    #pragma unroll
    for (int j = 0; j < 4; j++) {
        int c = side * 4 + j;
        sw[j] = (lr * 64 + ((c ^ (lr & 7)) * 8)) * 2;
    }

    auto fill = [&](int c, int s) {
        uint32_t as = sb + s * G_STGB;
        uint32_t bs = as + 16384;
        #pragma unroll
        for (int j = 0; j < 4; j++) {
            CP_ASYNC(as + sw[j], Ap + c * 64 + 8 * j);
            CP_ASYNC(bs + sw[j], Wp + c * 64 + 8 * j);
        }
        CP_COMMIT();
    };

    int tile = lane >> 3, rlow = lane & 7;
    int rowin = (tile & 1) * 8 + rlow;
    int chsel = tile >> 1;

    float acc[4][4][4];
    #pragma unroll
    for (int mt = 0; mt < 4; mt++)
        #pragma unroll
        for (int nt = 0; nt < 4; nt++)
            #pragma unroll
            for (int e = 0; e < 4; e++) acc[mt][nt][e] = 0.0f;

    int nk = K / 64;                 // 12
    fill(0, 0); fill(1, 1); fill(2, 2);

    for (int i = 0; i < nk; i++) {
        if (i == 0)           { CP_WAITN(2); }
        else if (i < nk - 1)  { CP_WAITN(1); }
        else                  { CP_WAITN(0); }
        __syncthreads();
        if (i >= 1 && i + 2 < nk) fill(i + 2, (i + 2) % 3);

        int s = i - (i / 3) * 3;
        uint32_t Ab = sb + s * G_STGB, Bb = Ab + 16384;
        #pragma unroll
        for (int ks = 0; ks < 4; ks++) {
            int chunk = ((2 * ks + chsel) ^ rlow) * 8;
            uint32_t af[4][4];
            #pragma unroll
            for (int mt = 0; mt < 4; mt++)
                ldmx4(af[mt], Ab + ((wm + mt * 16 + rowin) * 64 + chunk) * 2);
            #pragma unroll
            for (int g = 0; g < 2; g++) {
                uint32_t r4[4];
                ldmx4(r4, Bb + ((wn + g * 16 + rowin) * 64 + chunk) * 2);
                #pragma unroll
                for (int mt = 0; mt < 4; mt++) {
                    mma16816(acc[mt][2 * g],     af[mt], r4[0], r4[2]);
                    mma16816(acc[mt][2 * g + 1], af[mt], r4[1], r4[3]);
                }
            }
        }
    }

    // Epilogue
    #pragma unroll
    for (int mt = 0; mt < 4; mt++) {
        int row0 = m0 + wm + mt * 16 + gid;
        #pragma unroll
        for (int nt = 0; nt < 4; nt++) {
            int col = j0 + wn + nt * 8 + tig * 2;
            float b0 = bias[col], b1 = bias[col + 1];
            if (OUT_HALF) {
                __half* C = (__half*)Cv;
                *(uint32_t*)&C[(size_t)row0 * J + col] =
                    packh2(acc[mt][nt][0] + b0, acc[mt][nt][1] + b1);
                *(uint32_t*)&C[(size_t)(row0 + 8) * J + col] =
                    packh2(acc[mt][nt][2] + b0, acc[mt][nt][3] + b1);
            } else {
                float* C = (float*)Cv;
                *(float2*)&C[(size_t)row0 * J + col] =
                    make_float2(acc[mt][nt][0] + b0, acc[mt][nt][1] + b1);
                *(float2*)&C[(size_t)(row0 + 8) * J + col] =
                    make_float2(acc[mt][nt][2] + b0, acc[mt][nt][3] + b1);
            }
        }
    }
}

// ---------------------------------------------------------------------------
// Kernel 3: fused flash attention, fp16 MMA.
// Log2-domain softmax with ex2.approx.f16x2 (P born as fp16x2 A-frags);
// row-sum l accumulated by a ones-column HMMA in fp32; 3-stage cp.async K/V.
// smem: Q 16K | K 3x8K | V 3x8K | bias 4K | ones 512  = 70144 B
// ---------------------------------------------------------------------------
#define ATTN_SMEM 70144

__global__ void __launch_bounds__(256, 2)
attn_kernel(const float* __restrict__ biases) {
    extern __shared__ __align__(1024) char sma[];
    __half* Qh    = (__half*)sma;
    float*  b_s   = (float*)(sma + 65536);
    __half* ones_h = (__half*)(sma + 69632);
    uint32_t Qb = sptr(sma);
    uint32_t Kb = Qb + 16384;   // 3 stages of 8192 B
    uint32_t Vb = Qb + 40960;   // 3 stages of 8192 B
    uint32_t Ob = Qb + 69632;

    int qt = blockIdx.x, h = blockIdx.y, b = blockIdx.z;
    int tid = threadIdx.x, warp = tid >> 5, lane = tid & 31;
    int gid = lane >> 2, tig = lane & 3;
    int n0 = qt * 128;
    const float SCALE2 = SCALE_C * LOG2E;

    for (int i = tid; i < 1024; i += 256) b_s[i] = biases[h * 1024 + i] * LOG2E;

    // Stage Q [128 rows][64 dims], swizzled
    {
        int r = tid >> 1, side = tid & 1;
        const __half* qp = g_qkv + (size_t)(b * N_TOK + n0 + r) * QKVD
                           + h * 192 + side * 32;
        #pragma unroll
        for (int j = 0; j < 4; j++) {
            int c = side * 4 + j;
            *(uint4*)&Qh[r * 64 + ((c ^ (r & 7)) * 8)] =
                *(const uint4*)(qp + 8 * j);
        }
    }
    // ones tile [16 keys][16 dims], col 0 = 1
    if (tid < 16) {
        #pragma unroll
        for (int c = 0; c < 16; c++)
            ones_h[tid * 16 + c] = (c == 0) ? __float2half(1.0f)
                                            : __float2half(0.0f);
    }

    int tile = lane >> 3, rlow = lane & 7;
    int rowin = (tile & 1) * 8 + rlow;
    int chsel = tile >> 1;

    __syncthreads();
    uint32_t onesf[4];
    ldmx4t(onesf, Ob + rowin * 32 + chsel * 16);

    // K/V fill via cp.async (3-stage ring)
    int fr = tid >> 2, fq = tid & 3;
    uint32_t fsw[2];
    #pragma unroll
    for (int j = 0; j < 2; j++) {
        int c = fq * 2 + j;
        fsw[j] = (fr * 64 + ((c ^ (fr & 7)) * 8)) * 2;
    }
    auto fillkv = [&](int kt, int s) {
        const __half* kp = g_qkv + (size_t)(b * N_TOK + kt * 64 + fr) * QKVD
                           + h * 192 + 64 + fq * 16;
        const __half* vp = kp + 64;
        #pragma unroll
        for (int j = 0; j < 2; j++) {
            CP_ASYNC(Kb + s * 8192 + fsw[j], kp + 8 * j);
            CP_ASYNC(Vb + s * 8192 + fsw[j], vp + 8 * j);
        }
        CP_COMMIT();
    };

    float oacc[8][4], lacc[4];
    #pragma unroll
    for (int nt = 0; nt < 8; nt++)
        #pragma unroll
        for (int e = 0; e < 4; e++) oacc[nt][e] = 0.0f;
    #pragma unroll
    for (int e = 0; e < 4; e++) lacc[e] = 0.0f;
    float m0r = -1e30f, m1r = -1e30f;

    int q0 = n0 + warp * 16 + gid, q1 = q0 + 8;
    int yq0 = q0 >> 5, xq0 = q0 & 31;
    int yq1 = q1 >> 5, xq1 = q1 & 31;

    fillkv(0, 0); fillkv(1, 1);

    for (int kt = 0; kt < 16; kt++) {
        if (kt < 15) { CP_WAITN(1); }
        else         { CP_WAITN(0); }
        __syncthreads();
        if (kt + 2 < 16) fillkv(kt + 2, (kt + 2) % 3);

        int s = kt - (kt / 3) * 3;
        uint32_t Kcur = Kb + s * 8192;
        uint32_t Vcur = Vb + s * 8192;

        // S = Q @ K^T
        float sacc[8][4];
        #pragma unroll
        for (int nt = 0; nt < 8; nt++)
            #pragma unroll
            for (int e = 0; e < 4; e++) sacc[nt][e] = 0.0f;
        #pragma unroll
        for (int ks = 0; ks < 4; ks++) {
            int chunk = ((2 * ks + chsel) ^ rlow) * 8;
            uint32_t af[4];
            ldmx4(af, Qb + ((warp * 16 + rowin) * 64 + chunk) * 2);
            #pragma unroll
            for (int g = 0; g < 4; g++) {
                uint32_t r4[4];
                ldmx4(r4, Kcur + ((g * 16 + rowin) * 64 + chunk) * 2);
                mma16816(sacc[2 * g],     af, r4[0], r4[2]);
                mma16816(sacc[2 * g + 1], af, r4[1], r4[3]);
            }
        }

        // log2-domain: s' = s*SCALE*log2e + bias*log2e; row max
        float px0 = -1e30f, px1 = -1e30f;
        #pragma unroll
        for (int nt = 0; nt < 8; nt++) {
            #pragma unroll
            for (int e = 0; e < 2; e++) {
                int key = kt * 64 + nt * 8 + tig * 2 + e;
                int ym = key >> 5, xm = key & 31;
                float bv0 = b_s[abs(yq0 - ym) * 32 + abs(xq0 - xm)];
                float bv1 = b_s[abs(yq1 - ym) * 32 + abs(xq1 - xm)];
                sacc[nt][e]     = sacc[nt][e]     * SCALE2 + bv0;
                sacc[nt][e + 2] = sacc[nt][e + 2] * SCALE2 + bv1;
                px0 = fmaxf(px0, sacc[nt][e]);
                px1 = fmaxf(px1, sacc[nt][e + 2]);
            }
        }
        px0 = fmaxf(px0, __shfl_xor_sync(0xffffffffu, px0, 1));
        px0 = fmaxf(px0, __shfl_xor_sync(0xffffffffu, px0, 2));
        px1 = fmaxf(px1, __shfl_xor_sync(0xffffffffu, px1, 1));
        px1 = fmaxf(px1, __shfl_xor_sync(0xffffffffu, px1, 2));

        float mn0 = fmaxf(m0r, px0), mn1 = fmaxf(m1r, px1);
        float cr0 = ex2f(m0r - mn0), cr1 = ex2f(m1r - mn1);
        m0r = mn0; m1r = mn1;

        // P = 2^(s' - mn) directly as fp16x2 A-fragments
        uint32_t pfrag[4][4];
        #pragma unroll
        for (int c = 0; c < 4; c++) {
            pfrag[c][0] = ex2h2(packh2(sacc[2 * c][0] - mn0,
                                       sacc[2 * c][1] - mn0));
            pfrag[c][1] = ex2h2(packh2(sacc[2 * c][2] - mn1,
                                       sacc[2 * c][3] - mn1));
            pfrag[c][2] = ex2h2(packh2(sacc[2 * c + 1][0] - mn0,
                                       sacc[2 * c + 1][1] - mn0));
            pfrag[c][3] = ex2h2(packh2(sacc[2 * c + 1][2] - mn1,
                                       sacc[2 * c + 1][3] - mn1));
        }

        // rescale accumulators (lacc rides along)
        #pragma unroll
        for (int nt = 0; nt < 8; nt++) {
            oacc[nt][0] *= cr0; oacc[nt][1] *= cr0;
            oacc[nt][2] *= cr1; oacc[nt][3] *= cr1;
        }
        lacc[0] *= cr0; lacc[1] *= cr0; lacc[2] *= cr1; lacc[3] *= cr1;

        // O += P @ V ; l += P @ ones
        #pragma unroll
        for (int c = 0; c < 4; c++) {
            mma16816(lacc, pfrag[c], onesf[0], onesf[1]);
            #pragma unroll
            for (int g = 0; g < 4; g++) {
                uint32_t r4[4];
                int row = c * 16 + rowin;
                ldmx4t(r4, Vcur + (row * 64 + (((2 * g + chsel) ^ (row & 7)) * 8)) * 2);
                mma16816(oacc[2 * g],     pfrag[c], r4[0], r4[1]);
                mma16816(oacc[2 * g + 1], pfrag[c], r4[2], r4[3]);
            }
        }
    }

    // Epilogue: l lives in col 0 (tig==0); broadcast within each quad
    float l0 = __shfl_sync(0xffffffffu, lacc[0], lane & 28);
    float l1 = __shfl_sync(0xffffffffu, lacc[2], lane & 28);
    float inv0 = 1.0f / l0, inv1 = 1.0f / l1;
    size_t row0 = (size_t)(b * N_TOK + n0 + warp * 16 + gid) * DIM_N;
    size_t row1 = row0 + 8 * DIM_N;
    #pragma unroll
    for (int nt = 0; nt < 8; nt++) {
        int col = h * 64 + nt * 8 + tig * 2;
        *(uint32_t*)&g_att[row0 + col] =
            packh2(oacc[nt][0] * inv0, oacc[nt][1] * inv0);
        *(uint32_t*)&g_att[row1 + col] =
            packh2(oacc[nt][2] * inv1, oacc[nt][3] * inv1);
    }
}

// ---------------------------------------------------------------------------
extern "C" void kernel_launch(void* const* d_in, const int* in_sizes, int n_in,
                              void* d_out, int out_size) {
    const float* x           = (const float*)d_in[0];
    const float* ln_w        = (const float*)d_in[1];
    const float* ln_b        = (const float*)d_in[2];
    const float* qkv_w       = (const float*)d_in[3];
    const float* qkv_b       = (const float*)d_in[4];
    const float* proj_w      = (const float*)d_in[5];
    const float* proj_b      = (const float*)d_in[6];
    const float* attn_biases = (const float*)d_in[7];

    void *p_xn, *p_qkv, *p_att, *p_wq, *p_wp;
    cudaGetSymbolAddress(&p_xn, g_xn);
    cudaGetSymbolAddress(&p_qkv, g_qkv);
    cudaGetSymbolAddress(&p_att, g_att);
    cudaGetSymbolAddress(&p_wq, g_wq);
    cudaGetSymbolAddress(&p_wp, g_wp);

    cudaFuncSetAttribute(hgemm_bias<1>,
                         cudaFuncAttributeMaxDynamicSharedMemorySize, G_SMEM);
    cudaFuncSetAttribute(hgemm_bias<0>,
                         cudaFuncAttributeMaxDynamicSharedMemorySize, G_SMEM);
    cudaFuncSetAttribute(attn_kernel,
                         cudaFuncAttributeMaxDynamicSharedMemorySize, ATTN_SMEM);

    // 0. Weight conversion fp32 -> fp16
    cvt_f2h<<<(QKVD * DIM_N / 4 + 255) / 256, 256>>>(qkv_w, (__half*)p_wq,
                                                     QKVD * DIM_N);
    cvt_f2h<<<(DIM_N * DIM_N / 4 + 255) / 256, 256>>>(proj_w, (__half*)p_wp,
                                                      DIM_N * DIM_N);

    // 1. LayerNorm -> fp16
    ln_kernel<<<MROWS, 256>>>(x, ln_w, ln_b);

    // 2. QKV GEMM (fp16 HMMA): [16384,768] @ [2304,768]^T
    hgemm_bias<1><<<dim3(QKVD / 128, MROWS / 128), 256, G_SMEM>>>(
        (const __half*)p_xn, (const __half*)p_wq, qkv_b, p_qkv,
        MROWS, QKVD, DIM_N);

    // 3. Fused attention (fp16 HMMA, f16x2 exp, ones-MMA row sums)
    attn_kernel<<<dim3(N_TOK / 128, H_N, B_N), 256, ATTN_SMEM>>>(attn_biases);

    // 4. Projection GEMM (fp16 HMMA) -> fp32 output
    hgemm_bias<0><<<dim3(DIM_N / 128, MROWS / 128), 256, G_SMEM>>>(
        (const __half*)p_att, (const __half*)p_wp, proj_b, d_out,
        MROWS, DIM_N, DIM_N);
}

// round 9
// speedup vs baseline: 1.3272x; 1.0070x over previous
#include <cuda_runtime.h>
#include <cuda_fp16.h>
#include <math.h>
#include <stdint.h>

// Problem constants
#define B_N   16
#define N_TOK 1024
#define DIM_N 768
#define H_N   12
#define QKVD  2304
#define MROWS 16384
#define SCALE_C 0.125f
#define LOG2E 1.4426950408889634f
#define LN_EPS  1e-5f

// Scratch (device globals — no dynamic allocation allowed). All fp16.
__device__ __half g_xn[(size_t)MROWS * DIM_N];
__device__ __half g_qkv[(size_t)MROWS * QKVD];
__device__ __half g_att[(size_t)MROWS * DIM_N];
__device__ __half g_wq[(size_t)QKVD * DIM_N];
__device__ __half g_wp[(size_t)DIM_N * DIM_N];

// ---------------------------------------------------------------------------
// PTX helpers
// ---------------------------------------------------------------------------
__device__ __forceinline__ uint32_t sptr(const void* p) {
    return (uint32_t)__cvta_generic_to_shared(p);
}
__device__ __forceinline__ void ldmx4(uint32_t* r, uint32_t a) {
    asm volatile("ldmatrix.sync.aligned.m8n8.x4.shared.b16 {%0,%1,%2,%3}, [%4];"
                 : "=r"(r[0]), "=r"(r[1]), "=r"(r[2]), "=r"(r[3]) : "r"(a));
}
__device__ __forceinline__ void ldmx4t(uint32_t* r, uint32_t a) {
    asm volatile("ldmatrix.sync.aligned.m8n8.x4.trans.shared.b16 {%0,%1,%2,%3}, [%4];"
                 : "=r"(r[0]), "=r"(r[1]), "=r"(r[2]), "=r"(r[3]) : "r"(a));
}
__device__ __forceinline__ void mma16816(float* c, const uint32_t* a,
                                         uint32_t b0, uint32_t b1) {
    asm volatile(
        "mma.sync.aligned.m16n8k16.row.col.f32.f16.f16.f32 "
        "{%0,%1,%2,%3}, {%4,%5,%6,%7}, {%8,%9}, {%0,%1,%2,%3};"
        : "+f"(c[0]), "+f"(c[1]), "+f"(c[2]), "+f"(c[3])
        : "r"(a[0]), "r"(a[1]), "r"(a[2]), "r"(a[3]), "r"(b0), "r"(b1));
}
__device__ __forceinline__ uint32_t packh2(float x, float y) {
    __half2 h = __floats2half2_rn(x, y);
    return *(uint32_t*)&h;
}
__device__ __forceinline__ uint32_t ex2h2(uint32_t x) {
    uint32_t r;
    asm("ex2.approx.f16x2 %0, %1;" : "=r"(r) : "r"(x));
    return r;
}
__device__ __forceinline__ float ex2f(float x) {
    float r;
    asm("ex2.approx.f32 %0, %1;" : "=f"(r) : "f"(x));
    return r;
}
#define CP_ASYNC(dst, src) \
    asm volatile("cp.async.cg.shared.global [%0], [%1], 16;" :: "r"(dst), "l"(src))
#define CP_COMMIT() asm volatile("cp.async.commit_group;")
#define CP_WAITN(n) asm volatile("cp.async.wait_group %0;" :: "n"(n))

// ---------------------------------------------------------------------------
// Kernel 0: fp32 -> fp16 weight conversion
// ---------------------------------------------------------------------------
__global__ void cvt_f2h(const float* __restrict__ s, __half* __restrict__ d,
                        int n) {
    int i = (blockIdx.x * 256 + threadIdx.x) * 4;
    if (i < n) {
        float4 v = *(const float4*)(s + i);
        *(__half2*)(d + i)     = __floats2half2_rn(v.x, v.y);
        *(__half2*)(d + i + 2) = __floats2half2_rn(v.z, v.w);
    }
}

// ---------------------------------------------------------------------------
// Kernel 1: LayerNorm -> fp16 output. One block per row. 256 threads.
// ---------------------------------------------------------------------------
__global__ void ln_kernel(const float* __restrict__ x,
                          const float* __restrict__ w,
                          const float* __restrict__ b) {
    int row = blockIdx.x;
    const float* xr = x + (size_t)row * DIM_N;
    int t = threadIdx.x;
    float v0 = xr[t], v1 = xr[t + 256], v2 = xr[t + 512];
    float s  = v0 + v1 + v2;
    float sq = v0 * v0 + v1 * v1 + v2 * v2;
    #pragma unroll
    for (int o = 16; o; o >>= 1) {
        s  += __shfl_xor_sync(0xffffffffu, s, o);
        sq += __shfl_xor_sync(0xffffffffu, sq, o);
    }
    __shared__ float ss[8], ssq[8];
    int wid = t >> 5, lid = t & 31;
    if (lid == 0) { ss[wid] = s; ssq[wid] = sq; }
    __syncthreads();
    if (wid == 0) {
        s = ss[lid & 7]; sq = ssq[lid & 7];
        #pragma unroll
        for (int o = 4; o; o >>= 1) {
            s  += __shfl_xor_sync(0xffffffffu, s, o);
            sq += __shfl_xor_sync(0xffffffffu, sq, o);
        }
        if (lid == 0) { ss[0] = s; ssq[0] = sq; }
    }
    __syncthreads();
    float mean = ss[0] * (1.0f / DIM_N);
    float var  = ssq[0] * (1.0f / DIM_N) - mean * mean;
    float rstd = rsqrtf(var + LN_EPS);
    __half* o = g_xn + (size_t)row * DIM_N;
    int c = t;
    o[c] = __float2half((v0 - mean) * rstd * w[c] + b[c]); c += 256;
    o[c] = __float2half((v1 - mean) * rstd * w[c] + b[c]); c += 256;
    o[c] = __float2half((v2 - mean) * rstd * w[c] + b[c]);
}

// ---------------------------------------------------------------------------
// Kernel 2/4: fp16 HMMA GEMM  C[M,J] = A[M,K] @ W[J,K]^T + bias[J]
// 128x128 tile, BK=64, 8 warps (2x4), warp 64x32, 3-stage cp.async ring,
// one barrier per chunk; B-fragment ping-pong across ks-steps.
// ---------------------------------------------------------------------------
#define G_STGB 32768            // per stage: A 16KB + B 16KB
#define G_SMEM (3 * G_STGB)     // 96 KB

template <int OUT_HALF>
__global__ void __launch_bounds__(256, 2)
hgemm_bias(const __half* __restrict__ A, const __half* __restrict__ W,
           const float* __restrict__ bias, void* __restrict__ Cv,
           int M, int J, int K) {
    extern __shared__ __align__(1024) char smg[];
    uint32_t sb = sptr(smg);

    int m0 = blockIdx.y * 128, j0 = blockIdx.x * 128;
    int tid = threadIdx.x, warp = tid >> 5, lane = tid & 31;
    int gid = lane >> 2, tig = lane & 3;
    int wm = (warp >> 2) * 64, wn = (warp & 3) * 32;
    int lr = tid >> 1, side = tid & 1;

    const __half* Ap = A + (size_t)(m0 + lr) * K + side * 32;
    const __half* Wp = W + (size_t)(j0 + lr) * K + side * 32;

    uint32_t sw[4];
    #pragma unroll
    for (int j = 0; j < 4; j++) {
        int c = side * 4 + j;
        sw[j] = (lr * 64 + ((c ^ (lr & 7)) * 8)) * 2;
    }

    auto fill = [&](int c, int s) {
        uint32_t as = sb + s * G_STGB;
        uint32_t bs = as + 16384;
        #pragma unroll
        for (int j = 0; j < 4; j++) {
            CP_ASYNC(as + sw[j], Ap + c * 64 + 8 * j);
            CP_ASYNC(bs + sw[j], Wp + c * 64 + 8 * j);
        }
        CP_COMMIT();
    };

    int tile = lane >> 3, rlow = lane & 7;
    int rowin = (tile & 1) * 8 + rlow;
    int chsel = tile >> 1;

    float acc[4][4][4];
    #pragma unroll
    for (int mt = 0; mt < 4; mt++)
        #pragma unroll
        for (int nt = 0; nt < 4; nt++)
            #pragma unroll
            for (int e = 0; e < 4; e++) acc[mt][nt][e] = 0.0f;

    int nk = K / 64;                 // 12
    fill(0, 0); fill(1, 1); fill(2, 2);

    for (int i = 0; i < nk; i++) {
        if (i == 0)           { CP_WAITN(2); }
        else if (i < nk - 1)  { CP_WAITN(1); }
        else                  { CP_WAITN(0); }
        __syncthreads();
        if (i >= 1 && i + 2 < nk) fill(i + 2, (i + 2) % 3);

        int s = i - (i / 3) * 3;
        uint32_t Ab = sb + s * G_STGB, Bb = Ab + 16384;

        uint32_t bfr[2][8];
        {
            int ch0 = (chsel ^ rlow) * 8;   // ks = 0
            ldmx4(&bfr[0][0], Bb + ((wn + rowin) * 64 + ch0) * 2);
            ldmx4(&bfr[0][4], Bb + ((wn + 16 + rowin) * 64 + ch0) * 2);
        }
        #pragma unroll
        for (int ks = 0; ks < 4; ks++) {
            int cur = ks & 1;
            int chunk = ((2 * ks + chsel) ^ rlow) * 8;
            uint32_t af[4][4];
            #pragma unroll
            for (int mt = 0; mt < 4; mt++)
                ldmx4(af[mt], Ab + ((wm + mt * 16 + rowin) * 64 + chunk) * 2);
            if (ks < 3) {
                int chn = ((2 * (ks + 1) + chsel) ^ rlow) * 8;
                ldmx4(&bfr[cur ^ 1][0], Bb + ((wn + rowin) * 64 + chn) * 2);
                ldmx4(&bfr[cur ^ 1][4], Bb + ((wn + 16 + rowin) * 64 + chn) * 2);
            }
            #pragma unroll
            for (int g = 0; g < 2; g++) {
                const uint32_t* r4 = &bfr[cur][g * 4];
                #pragma unroll
                for (int mt = 0; mt < 4; mt++) {
                    mma16816(acc[mt][2 * g],     af[mt], r4[0], r4[2]);
                    mma16816(acc[mt][2 * g + 1], af[mt], r4[1], r4[3]);
                }
            }
        }
    }

    // Epilogue
    #pragma unroll
    for (int mt = 0; mt < 4; mt++) {
        int row0 = m0 + wm + mt * 16 + gid;
        #pragma unroll
        for (int nt = 0; nt < 4; nt++) {
            int col = j0 + wn + nt * 8 + tig * 2;
            float b0 = bias[col], b1 = bias[col + 1];
            if (OUT_HALF) {
                __half* C = (__half*)Cv;
                *(uint32_t*)&C[(size_t)row0 * J + col] =
                    packh2(acc[mt][nt][0] + b0, acc[mt][nt][1] + b1);
                *(uint32_t*)&C[(size_t)(row0 + 8) * J + col] =
                    packh2(acc[mt][nt][2] + b0, acc[mt][nt][3] + b1);
            } else {
                float* C = (float*)Cv;
                *(float2*)&C[(size_t)row0 * J + col] =
                    make_float2(acc[mt][nt][0] + b0, acc[mt][nt][1] + b1);
                *(float2*)&C[(size_t)(row0 + 8) * J + col] =
                    make_float2(acc[mt][nt][2] + b0, acc[mt][nt][3] + b1);
            }
        }
    }
}

// ---------------------------------------------------------------------------
// Kernel 3: fused flash attention, fp16 MMA.
// Log2-domain softmax (ex2.approx.f16x2), ones-column MMA row sums,
// 3-stage cp.async K/V ring, stride-33 bias table (conflict-free LDS).
// smem: Q 16K | K 3x8K | V 3x8K | bias 32x33 f32 (4224B) | ones 512B
// ---------------------------------------------------------------------------
#define ATTN_SMEM 70400

__global__ void __launch_bounds__(256, 2)
attn_kernel(const float* __restrict__ biases) {
    extern __shared__ __align__(1024) char sma[];
    __half* Qh     = (__half*)sma;
    float*  b_s    = (float*)(sma + 65536);       // 32*33 floats, stride 33
    __half* ones_h = (__half*)(sma + 69824);
    uint32_t Qb = sptr(sma);
    uint32_t Kb = Qb + 16384;   // 3 stages of 8192 B
    uint32_t Vb = Qb + 40960;   // 3 stages of 8192 B
    uint32_t Ob = Qb + 69824;

    int qt = blockIdx.x, h = blockIdx.y, b = blockIdx.z;
    int tid = threadIdx.x, warp = tid >> 5, lane = tid & 31;
    int gid = lane >> 2, tig = lane & 3;
    int n0 = qt * 128;
    const float SCALE2 = SCALE_C * LOG2E;

    for (int i = tid; i < 1024; i += 256) {
        int dy = i >> 5, dx = i & 31;
        b_s[dy * 33 + dx] = biases[h * 1024 + i] * LOG2E;
    }

    // Stage Q [128 rows][64 dims], swizzled
    {
        int r = tid >> 1, side = tid & 1;
        const __half* qp = g_qkv + (size_t)(b * N_TOK + n0 + r) * QKVD
                           + h * 192 + side * 32;
        #pragma unroll
        for (int j = 0; j < 4; j++) {
            int c = side * 4 + j;
            *(uint4*)&Qh[r * 64 + ((c ^ (r & 7)) * 8)] =
                *(const uint4*)(qp + 8 * j);
        }
    }
    // ones tile [16 keys][16 dims], col 0 = 1
    if (tid < 16) {
        #pragma unroll
        for (int c = 0; c < 16; c++)
            ones_h[tid * 16 + c] = (c == 0) ? __float2half(1.0f)
                                            : __float2half(0.0f);
    }

    int tile = lane >> 3, rlow = lane & 7;
    int rowin = (tile & 1) * 8 + rlow;
    int chsel = tile >> 1;

    __syncthreads();
    uint32_t onesf[4];
    ldmx4t(onesf, Ob + rowin * 32 + chsel * 16);

    // K/V fill via cp.async (3-stage ring)
    int fr = tid >> 2, fq = tid & 3;
    uint32_t fsw[2];
    #pragma unroll
    for (int j = 0; j < 2; j++) {
        int c = fq * 2 + j;
        fsw[j] = (fr * 64 + ((c ^ (fr & 7)) * 8)) * 2;
    }
    auto fillkv = [&](int kt, int s) {
        const __half* kp = g_qkv + (size_t)(b * N_TOK + kt * 64 + fr) * QKVD
                           + h * 192 + 64 + fq * 16;
        const __half* vp = kp + 64;
        #pragma unroll
        for (int j = 0; j < 2; j++) {
            CP_ASYNC(Kb + s * 8192 + fsw[j], kp + 8 * j);
            CP_ASYNC(Vb + s * 8192 + fsw[j], vp + 8 * j);
        }
        CP_COMMIT();
    };

    float oacc[8][4], lacc[4];
    #pragma unroll
    for (int nt = 0; nt < 8; nt++)
        #pragma unroll
        for (int e = 0; e < 4; e++) oacc[nt][e] = 0.0f;
    #pragma unroll
    for (int e = 0; e < 4; e++) lacc[e] = 0.0f;
    float m0r = -1e30f, m1r = -1e30f;

    int q0 = n0 + warp * 16 + gid, q1 = q0 + 8;
    int yq0 = q0 >> 5, xq0 = q0 & 31;
    int yq1 = q1 >> 5, xq1 = q1 & 31;

    fillkv(0, 0); fillkv(1, 1);

    for (int kt = 0; kt < 16; kt++) {
        if (kt < 15) { CP_WAITN(1); }
        else         { CP_WAITN(0); }
        __syncthreads();
        if (kt + 2 < 16) fillkv(kt + 2, (kt + 2) % 3);

        int s = kt - (kt / 3) * 3;
        uint32_t Kcur = Kb + s * 8192;
        uint32_t Vcur = Vb + s * 8192;

        // S = Q @ K^T
        float sacc[8][4];
        #pragma unroll
        for (int nt = 0; nt < 8; nt++)
            #pragma unroll
            for (int e = 0; e < 4; e++) sacc[nt][e] = 0.0f;
        #pragma unroll
        for (int ks = 0; ks < 4; ks++) {
            int chunk = ((2 * ks + chsel) ^ rlow) * 8;
            uint32_t af[4];
            ldmx4(af, Qb + ((warp * 16 + rowin) * 64 + chunk) * 2);
            #pragma unroll
            for (int g = 0; g < 4; g++) {
                uint32_t r4[4];
                ldmx4(r4, Kcur + ((g * 16 + rowin) * 64 + chunk) * 2);
                mma16816(sacc[2 * g],     af, r4[0], r4[2]);
                mma16816(sacc[2 * g + 1], af, r4[1], r4[3]);
            }
        }

        // log2-domain: s' = s*SCALE*log2e + bias*log2e; row max
        float px0 = -1e30f, px1 = -1e30f;
        #pragma unroll
        for (int nt = 0; nt < 8; nt++) {
            #pragma unroll
            for (int e = 0; e < 2; e++) {
                int key = kt * 64 + nt * 8 + tig * 2 + e;
                int ym = key >> 5, xm = key & 31;
                float bv0 = b_s[abs(yq0 - ym) * 33 + abs(xq0 - xm)];
                float bv1 = b_s[abs(yq1 - ym) * 33 + abs(xq1 - xm)];
                sacc[nt][e]     = sacc[nt][e]     * SCALE2 + bv0;
                sacc[nt][e + 2] = sacc[nt][e + 2] * SCALE2 + bv1;
                px0 = fmaxf(px0, sacc[nt][e]);
                px1 = fmaxf(px1, sacc[nt][e + 2]);
            }
        }
        px0 = fmaxf(px0, __shfl_xor_sync(0xffffffffu, px0, 1));
        px0 = fmaxf(px0, __shfl_xor_sync(0xffffffffu, px0, 2));
        px1 = fmaxf(px1, __shfl_xor_sync(0xffffffffu, px1, 1));
        px1 = fmaxf(px1, __shfl_xor_sync(0xffffffffu, px1, 2));

        float mn0 = fmaxf(m0r, px0), mn1 = fmaxf(m1r, px1);
        float cr0 = ex2f(m0r - mn0), cr1 = ex2f(m1r - mn1);
        m0r = mn0; m1r = mn1;

        // P = 2^(s' - mn) directly as fp16x2 A-fragments
        uint32_t pfrag[4][4];
        #pragma unroll
        for (int c = 0; c < 4; c++) {
            pfrag[c][0] = ex2h2(packh2(sacc[2 * c][0] - mn0,
                                       sacc[2 * c][1] - mn0));
            pfrag[c][1] = ex2h2(packh2(sacc[2 * c][2] - mn1,
                                       sacc[2 * c][3] - mn1));
            pfrag[c][2] = ex2h2(packh2(sacc[2 * c + 1][0] - mn0,
                                       sacc[2 * c + 1][1] - mn0));
            pfrag[c][3] = ex2h2(packh2(sacc[2 * c + 1][2] - mn1,
                                       sacc[2 * c + 1][3] - mn1));
        }

        // rescale accumulators (lacc rides along)
        #pragma unroll
        for (int nt = 0; nt < 8; nt++) {
            oacc[nt][0] *= cr0; oacc[nt][1] *= cr0;
            oacc[nt][2] *= cr1; oacc[nt][3] *= cr1;
        }
        lacc[0] *= cr0; lacc[1] *= cr0; lacc[2] *= cr1; lacc[3] *= cr1;

        // O += P @ V ; l += P @ ones
        #pragma unroll
        for (int c = 0; c < 4; c++) {
            mma16816(lacc, pfrag[c], onesf[0], onesf[1]);
            #pragma unroll
            for (int g = 0; g < 4; g++) {
                uint32_t r4[4];
                int row = c * 16 + rowin;
                ldmx4t(r4, Vcur + (row * 64 + (((2 * g + chsel) ^ (row & 7)) * 8)) * 2);
                mma16816(oacc[2 * g],     pfrag[c], r4[0], r4[1]);
                mma16816(oacc[2 * g + 1], pfrag[c], r4[2], r4[3]);
            }
        }
    }

    // Epilogue: l lives in col 0 (tig==0); broadcast within each quad
    float l0 = __shfl_sync(0xffffffffu, lacc[0], lane & 28);
    float l1 = __shfl_sync(0xffffffffu, lacc[2], lane & 28);
    float inv0 = 1.0f / l0, inv1 = 1.0f / l1;
    size_t row0 = (size_t)(b * N_TOK + n0 + warp * 16 + gid) * DIM_N;
    size_t row1 = row0 + 8 * DIM_N;
    #pragma unroll
    for (int nt = 0; nt < 8; nt++) {
        int col = h * 64 + nt * 8 + tig * 2;
        *(uint32_t*)&g_att[row0 + col] =
            packh2(oacc[nt][0] * inv0, oacc[nt][1] * inv0);
        *(uint32_t*)&g_att[row1 + col] =
            packh2(oacc[nt][2] * inv1, oacc[nt][3] * inv1);
    }
}

// ---------------------------------------------------------------------------
extern "C" void kernel_launch(void* const* d_in, const int* in_sizes, int n_in,
                              void* d_out, int out_size) {
    const float* x           = (const float*)d_in[0];
    const float* ln_w        = (const float*)d_in[1];
    const float* ln_b        = (const float*)d_in[2];
    const float* qkv_w       = (const float*)d_in[3];
    const float* qkv_b       = (const float*)d_in[4];
    const float* proj_w      = (const float*)d_in[5];
    const float* proj_b      = (const float*)d_in[6];
    const float* attn_biases = (const float*)d_in[7];

    void *p_xn, *p_qkv, *p_att, *p_wq, *p_wp;
    cudaGetSymbolAddress(&p_xn, g_xn);
    cudaGetSymbolAddress(&p_qkv, g_qkv);
    cudaGetSymbolAddress(&p_att, g_att);
    cudaGetSymbolAddress(&p_wq, g_wq);
    cudaGetSymbolAddress(&p_wp, g_wp);

    cudaFuncSetAttribute(hgemm_bias<1>,
                         cudaFuncAttributeMaxDynamicSharedMemorySize, G_SMEM);
    cudaFuncSetAttribute(hgemm_bias<0>,
                         cudaFuncAttributeMaxDynamicSharedMemorySize, G_SMEM);
    cudaFuncSetAttribute(attn_kernel,
                         cudaFuncAttributeMaxDynamicSharedMemorySize, ATTN_SMEM);

    // 0. Weight conversion fp32 -> fp16
    cvt_f2h<<<(QKVD * DIM_N / 4 + 255) / 256, 256>>>(qkv_w, (__half*)p_wq,
                                                     QKVD * DIM_N);
    cvt_f2h<<<(DIM_N * DIM_N / 4 + 255) / 256, 256>>>(proj_w, (__half*)p_wp,
                                                      DIM_N * DIM_N);

    // 1. LayerNorm -> fp16
    ln_kernel<<<MROWS, 256>>>(x, ln_w, ln_b);

    // 2. QKV GEMM (fp16 HMMA): [16384,768] @ [2304,768]^T
    hgemm_bias<1><<<dim3(QKVD / 128, MROWS / 128), 256, G_SMEM>>>(
        (const __half*)p_xn, (const __half*)p_wq, qkv_b, p_qkv,
        MROWS, QKVD, DIM_N);

    // 3. Fused attention
    attn_kernel<<<dim3(N_TOK / 128, H_N, B_N), 256, ATTN_SMEM>>>(attn_biases);

    // 4. Projection GEMM (fp16 HMMA) -> fp32 output
    hgemm_bias<0><<<dim3(DIM_N / 128, MROWS / 128), 256, G_SMEM>>>(
        (const __half*)p_att, (const __half*)p_wp, proj_b, d_out,
        MROWS, DIM_N, DIM_N);
}

// round 10
// speedup vs baseline: 1.4096x; 1.0621x over previous
#include <cuda_runtime.h>
#include <cuda_fp16.h>
#include <math.h>
#include <stdint.h>

// Problem constants
#define B_N   16
#define N_TOK 1024
#define DIM_N 768
#define H_N   12
#define QKVD  2304
#define MROWS 16384
#define SCALE_C 0.125f
#define LOG2E 1.4426950408889634f
#define MSHIFT 4.0f
#define LN_EPS  1e-5f

// Scratch (device globals — no dynamic allocation allowed). All fp16.
__device__ __half g_xn[(size_t)MROWS * DIM_N];
__device__ __half g_qkv[(size_t)MROWS * QKVD];
__device__ __half g_att[(size_t)MROWS * DIM_N];
__device__ __half g_wq[(size_t)QKVD * DIM_N];
__device__ __half g_wp[(size_t)DIM_N * DIM_N];

// ---------------------------------------------------------------------------
// PTX helpers
// ---------------------------------------------------------------------------
__device__ __forceinline__ uint32_t sptr(const void* p) {
    return (uint32_t)__cvta_generic_to_shared(p);
}
__device__ __forceinline__ void ldmx4(uint32_t* r, uint32_t a) {
    asm volatile("ldmatrix.sync.aligned.m8n8.x4.shared.b16 {%0,%1,%2,%3}, [%4];"
                 : "=r"(r[0]), "=r"(r[1]), "=r"(r[2]), "=r"(r[3]) : "r"(a));
}
__device__ __forceinline__ void ldmx4t(uint32_t* r, uint32_t a) {
    asm volatile("ldmatrix.sync.aligned.m8n8.x4.trans.shared.b16 {%0,%1,%2,%3}, [%4];"
                 : "=r"(r[0]), "=r"(r[1]), "=r"(r[2]), "=r"(r[3]) : "r"(a));
}
__device__ __forceinline__ void mma16816(float* c, const uint32_t* a,
                                         uint32_t b0, uint32_t b1) {
    asm volatile(
        "mma.sync.aligned.m16n8k16.row.col.f32.f16.f16.f32 "
        "{%0,%1,%2,%3}, {%4,%5,%6,%7}, {%8,%9}, {%0,%1,%2,%3};"
        : "+f"(c[0]), "+f"(c[1]), "+f"(c[2]), "+f"(c[3])
        : "r"(a[0]), "r"(a[1]), "r"(a[2]), "r"(a[3]), "r"(b0), "r"(b1));
}
__device__ __forceinline__ uint32_t packh2(float x, float y) {
    __half2 h = __floats2half2_rn(x, y);
    return *(uint32_t*)&h;
}
__device__ __forceinline__ uint32_t ex2h2(uint32_t x) {
    uint32_t r;
    asm("ex2.approx.f16x2 %0, %1;" : "=r"(r) : "r"(x));
    return r;
}
#define CP_ASYNC(dst, src) \
    asm volatile("cp.async.cg.shared.global [%0], [%1], 16;" :: "r"(dst), "l"(src))
#define CP_COMMIT() asm volatile("cp.async.commit_group;")
#define CP_WAITN(n) asm volatile("cp.async.wait_group %0;" :: "n"(n))

// ---------------------------------------------------------------------------
// Kernel 0: fp32 -> fp16 weight conversion
// ---------------------------------------------------------------------------
__global__ void cvt_f2h(const float* __restrict__ s, __half* __restrict__ d,
                        int n) {
    int i = (blockIdx.x * 256 + threadIdx.x) * 4;
    if (i < n) {
        float4 v = *(const float4*)(s + i);
        *(__half2*)(d + i)     = __floats2half2_rn(v.x, v.y);
        *(__half2*)(d + i + 2) = __floats2half2_rn(v.z, v.w);
    }
}

// ---------------------------------------------------------------------------
// Kernel 1: LayerNorm -> fp16 output. One block per row. 256 threads.
// ---------------------------------------------------------------------------
__global__ void ln_kernel(const float* __restrict__ x,
                          const float* __restrict__ w,
                          const float* __restrict__ b) {
    int row = blockIdx.x;
    const float* xr = x + (size_t)row * DIM_N;
    int t = threadIdx.x;
    float v0 = xr[t], v1 = xr[t + 256], v2 = xr[t + 512];
    float s  = v0 + v1 + v2;
    float sq = v0 * v0 + v1 * v1 + v2 * v2;
    #pragma unroll
    for (int o = 16; o; o >>= 1) {
        s  += __shfl_xor_sync(0xffffffffu, s, o);
        sq += __shfl_xor_sync(0xffffffffu, sq, o);
    }
    __shared__ float ss[8], ssq[8];
    int wid = t >> 5, lid = t & 31;
    if (lid == 0) { ss[wid] = s; ssq[wid] = sq; }
    __syncthreads();
    if (wid == 0) {
        s = ss[lid & 7]; sq = ssq[lid & 7];
        #pragma unroll
        for (int o = 4; o; o >>= 1) {
            s  += __shfl_xor_sync(0xffffffffu, s, o);
            sq += __shfl_xor_sync(0xffffffffu, sq, o);
        }
        if (lid == 0) { ss[0] = s; ssq[0] = sq; }
    }
    __syncthreads();
    float mean = ss[0] * (1.0f / DIM_N);
    float var  = ssq[0] * (1.0f / DIM_N) - mean * mean;
    float rstd = rsqrtf(var + LN_EPS);
    __half* o = g_xn + (size_t)row * DIM_N;
    int c = t;
    o[c] = __float2half((v0 - mean) * rstd * w[c] + b[c]); c += 256;
    o[c] = __float2half((v1 - mean) * rstd * w[c] + b[c]); c += 256;
    o[c] = __float2half((v2 - mean) * rstd * w[c] + b[c]);
}

// ---------------------------------------------------------------------------
// Kernel 2/4: fp16 HMMA GEMM  C[M,J] = A[M,K] @ W[J,K]^T + bias[J]
// 128x128 tile, BK=64, 8 warps (2x4), warp 64x32, 3-stage cp.async ring,
// one barrier per chunk; B-fragment ping-pong across ks-steps.
// ---------------------------------------------------------------------------
#define G_STGB 32768            // per stage: A 16KB + B 16KB
#define G_SMEM (3 * G_STGB)     // 96 KB

template <int OUT_HALF>
__global__ void __launch_bounds__(256, 2)
hgemm_bias(const __half* __restrict__ A, const __half* __restrict__ W,
           const float* __restrict__ bias, void* __restrict__ Cv,
           int M, int J, int K) {
    extern __shared__ __align__(1024) char smg[];
    uint32_t sb = sptr(smg);

    int m0 = blockIdx.y * 128, j0 = blockIdx.x * 128;
    int tid = threadIdx.x, warp = tid >> 5, lane = tid & 31;
    int gid = lane >> 2, tig = lane & 3;
    int wm = (warp >> 2) * 64, wn = (warp & 3) * 32;
    int lr = tid >> 1, side = tid & 1;

    const __half* Ap = A + (size_t)(m0 + lr) * K + side * 32;
    const __half* Wp = W + (size_t)(j0 + lr) * K + side * 32;

    uint32_t sw[4];
    #pragma unroll
    for (int j = 0; j < 4; j++) {
        int c = side * 4 + j;
        sw[j] = (lr * 64 + ((c ^ (lr & 7)) * 8)) * 2;
    }

    auto fill = [&](int c, int s) {
        uint32_t as = sb + s * G_STGB;
        uint32_t bs = as + 16384;
        #pragma unroll
        for (int j = 0; j < 4; j++) {
            CP_ASYNC(as + sw[j], Ap + c * 64 + 8 * j);
            CP_ASYNC(bs + sw[j], Wp + c * 64 + 8 * j);
        }
        CP_COMMIT();
    };

    int tile = lane >> 3, rlow = lane & 7;
    int rowin = (tile & 1) * 8 + rlow;
    int chsel = tile >> 1;

    float acc[4][4][4];
    #pragma unroll
    for (int mt = 0; mt < 4; mt++)
        #pragma unroll
        for (int nt = 0; nt < 4; nt++)
            #pragma unroll
            for (int e = 0; e < 4; e++) acc[mt][nt][e] = 0.0f;

    int nk = K / 64;                 // 12
    fill(0, 0); fill(1, 1); fill(2, 2);

    for (int i = 0; i < nk; i++) {
        if (i == 0)           { CP_WAITN(2); }
        else if (i < nk - 1)  { CP_WAITN(1); }
        else                  { CP_WAITN(0); }
        __syncthreads();
        if (i >= 1 && i + 2 < nk) fill(i + 2, (i + 2) % 3);

        int s = i - (i / 3) * 3;
        uint32_t Ab = sb + s * G_STGB, Bb = Ab + 16384;

        uint32_t bfr[2][8];
        {
            int ch0 = (chsel ^ rlow) * 8;   // ks = 0
            ldmx4(&bfr[0][0], Bb + ((wn + rowin) * 64 + ch0) * 2);
            ldmx4(&bfr[0][4], Bb + ((wn + 16 + rowin) * 64 + ch0) * 2);
        }
        #pragma unroll
        for (int ks = 0; ks < 4; ks++) {
            int cur = ks & 1;
            int chunk = ((2 * ks + chsel) ^ rlow) * 8;
            uint32_t af[4][4];
            #pragma unroll
            for (int mt = 0; mt < 4; mt++)
                ldmx4(af[mt], Ab + ((wm + mt * 16 + rowin) * 64 + chunk) * 2);
            if (ks < 3) {
                int chn = ((2 * (ks + 1) + chsel) ^ rlow) * 8;
                ldmx4(&bfr[cur ^ 1][0], Bb + ((wn + rowin) * 64 + chn) * 2);
                ldmx4(&bfr[cur ^ 1][4], Bb + ((wn + 16 + rowin) * 64 + chn) * 2);
            }
            #pragma unroll
            for (int g = 0; g < 2; g++) {
                const uint32_t* r4 = &bfr[cur][g * 4];
                #pragma unroll
                for (int mt = 0; mt < 4; mt++) {
                    mma16816(acc[mt][2 * g],     af[mt], r4[0], r4[2]);
                    mma16816(acc[mt][2 * g + 1], af[mt], r4[1], r4[3]);
                }
            }
        }
    }

    // Epilogue
    #pragma unroll
    for (int mt = 0; mt < 4; mt++) {
        int row0 = m0 + wm + mt * 16 + gid;
        #pragma unroll
        for (int nt = 0; nt < 4; nt++) {
            int col = j0 + wn + nt * 8 + tig * 2;
            float b0 = bias[col], b1 = bias[col + 1];
            if (OUT_HALF) {
                __half* C = (__half*)Cv;
                *(uint32_t*)&C[(size_t)row0 * J + col] =
                    packh2(acc[mt][nt][0] + b0, acc[mt][nt][1] + b1);
                *(uint32_t*)&C[(size_t)(row0 + 8) * J + col] =
                    packh2(acc[mt][nt][2] + b0, acc[mt][nt][3] + b1);
            } else {
                float* C = (float*)Cv;
                *(float2*)&C[(size_t)row0 * J + col] =
                    make_float2(acc[mt][nt][0] + b0, acc[mt][nt][1] + b1);
                *(float2*)&C[(size_t)(row0 + 8) * J + col] =
                    make_float2(acc[mt][nt][2] + b0, acc[mt][nt][3] + b1);
            }
        }
    }
}

// ---------------------------------------------------------------------------
// Kernel 3: fused flash attention, fp16 MMA.
// Static-shift log2 softmax (no running max): p = 2^(s*scale*log2e + b'),
// b' = bias*log2e - 4 folded into the (transposed, stride-33) bias table.
// Bias indexing hoisted: dx*33 precomputed per thread; per-iter = add+LDS.
// Q fragments hoisted out of the key loop. Ones-column MMA row sums.
// smem: Q 16K | K 3x8K | V 3x8K | bias 32x33 f32 (4224B) | ones 512B
// ---------------------------------------------------------------------------
#define ATTN_SMEM 70400

__global__ void __launch_bounds__(256, 2)
attn_kernel(const float* __restrict__ biases) {
    extern __shared__ __align__(1024) char sma[];
    __half* Qh     = (__half*)sma;
    float*  b_s    = (float*)(sma + 65536);       // transposed: [dx*33 + dy]
    __half* ones_h = (__half*)(sma + 69824);
    uint32_t Qb = sptr(sma);
    uint32_t Kb = Qb + 16384;   // 3 stages of 8192 B
    uint32_t Vb = Qb + 40960;   // 3 stages of 8192 B
    uint32_t Ob = Qb + 69824;

    int qt = blockIdx.x, h = blockIdx.y, b = blockIdx.z;
    int tid = threadIdx.x, warp = tid >> 5, lane = tid & 31;
    int gid = lane >> 2, tig = lane & 3;
    int n0 = qt * 128;
    const float SCALE2 = SCALE_C * LOG2E;

    // bias table: transposed, stride 33, with log2e scale and -MSHIFT folded
    for (int i = tid; i < 1024; i += 256) {
        int dy = i >> 5, dx = i & 31;
        b_s[dx * 33 + dy] = biases[h * 1024 + i] * LOG2E - MSHIFT;
    }

    // Stage Q [128 rows][64 dims], swizzled
    {
        int r = tid >> 1, side = tid & 1;
        const __half* qp = g_qkv + (size_t)(b * N_TOK + n0 + r) * QKVD
                           + h * 192 + side * 32;
        #pragma unroll
        for (int j = 0; j < 4; j++) {
            int c = side * 4 + j;
            *(uint4*)&Qh[r * 64 + ((c ^ (r & 7)) * 8)] =
                *(const uint4*)(qp + 8 * j);
        }
    }
    // ones tile [16 keys][16 dims], col 0 = 1
    if (tid < 16) {
        #pragma unroll
        for (int c = 0; c < 16; c++)
            ones_h[tid * 16 + c] = (c == 0) ? __float2half(1.0f)
                                            : __float2half(0.0f);
    }

    int tile = lane >> 3, rlow = lane & 7;
    int rowin = (tile & 1) * 8 + rlow;
    int chsel = tile >> 1;

    __syncthreads();
    uint32_t onesf[4];
    ldmx4t(onesf, Ob + rowin * 32 + chsel * 16);

    // Hoisted Q fragments (invariant across key tiles)
    uint32_t qfrag[4][4];
    #pragma unroll
    for (int ks = 0; ks < 4; ks++) {
        int chunk = ((2 * ks + chsel) ^ rlow) * 8;
        ldmx4(qfrag[ks], Qb + ((warp * 16 + rowin) * 64 + chunk) * 2);
    }

    // Precomputed dx*33 tables: v = (nt&3)*2 + e  ->  xm = (v>>1)*8 + tig*2 + (v&1)
    int q0 = n0 + warp * 16 + gid, q1 = q0 + 8;
    int yq0 = q0 >> 5, xq0 = q0 & 31;
    int yq1 = q1 >> 5, xq1 = q1 & 31;
    int dx0t[8], dx1t[8];
    #pragma unroll
    for (int v = 0; v < 8; v++) {
        int xm = (v >> 1) * 8 + tig * 2 + (v & 1);
        dx0t[v] = abs(xq0 - xm) * 33;
        dx1t[v] = abs(xq1 - xm) * 33;
    }

    // K/V fill via cp.async (3-stage ring)
    int fr = tid >> 2, fq = tid & 3;
    uint32_t fsw[2];
    #pragma unroll
    for (int j = 0; j < 2; j++) {
        int c = fq * 2 + j;
        fsw[j] = (fr * 64 + ((c ^ (fr & 7)) * 8)) * 2;
    }
    auto fillkv = [&](int kt, int s) {
        const __half* kp = g_qkv + (size_t)(b * N_TOK + kt * 64 + fr) * QKVD
                           + h * 192 + 64 + fq * 16;
        const __half* vp = kp + 64;
        #pragma unroll
        for (int j = 0; j < 2; j++) {
            CP_ASYNC(Kb + s * 8192 + fsw[j], kp + 8 * j);
            CP_ASYNC(Vb + s * 8192 + fsw[j], vp + 8 * j);
        }
        CP_COMMIT();
    };

    float oacc[8][4], lacc[4];
    #pragma unroll
    for (int nt = 0; nt < 8; nt++)
        #pragma unroll
        for (int e = 0; e < 4; e++) oacc[nt][e] = 0.0f;
    #pragma unroll
    for (int e = 0; e < 4; e++) lacc[e] = 0.0f;

    fillkv(0, 0); fillkv(1, 1);

    for (int kt = 0; kt < 16; kt++) {
        if (kt < 15) { CP_WAITN(1); }
        else         { CP_WAITN(0); }
        __syncthreads();
        if (kt + 2 < 16) fillkv(kt + 2, (kt + 2) % 3);

        int s = kt - (kt / 3) * 3;
        uint32_t Kcur = Kb + s * 8192;
        uint32_t Vcur = Vb + s * 8192;

        // S = Q @ K^T (Q frags from registers)
        float sacc[8][4];
        #pragma unroll
        for (int nt = 0; nt < 8; nt++)
            #pragma unroll
            for (int e = 0; e < 4; e++) sacc[nt][e] = 0.0f;
        #pragma unroll
        for (int ks = 0; ks < 4; ks++) {
            int chunk = ((2 * ks + chsel) ^ rlow) * 8;
            #pragma unroll
            for (int g = 0; g < 4; g++) {
                uint32_t r4[4];
                ldmx4(r4, Kcur + ((g * 16 + rowin) * 64 + chunk) * 2);
                mma16816(sacc[2 * g],     qfrag[ks], r4[0], r4[2]);
                mma16816(sacc[2 * g + 1], qfrag[ks], r4[1], r4[3]);
            }
        }

        // s' = s*SCALE2 + b' (bias lookup: add + LDS); dy recomputed per iter
        int dy0[2], dy1[2];
        #pragma unroll
        for (int yb = 0; yb < 2; yb++) {
            dy0[yb] = abs(yq0 - (2 * kt + yb));
            dy1[yb] = abs(yq1 - (2 * kt + yb));
        }
        #pragma unroll
        for (int nt = 0; nt < 8; nt++) {
            int yb = nt >> 2;
            #pragma unroll
            for (int e = 0; e < 2; e++) {
                int v = (nt & 3) * 2 + e;
                sacc[nt][e]     = sacc[nt][e]     * SCALE2 + b_s[dx0t[v] + dy0[yb]];
                sacc[nt][e + 2] = sacc[nt][e + 2] * SCALE2 + b_s[dx1t[v] + dy1[yb]];
            }
        }

        // P = 2^(s') directly as fp16x2 A-fragments (static shift, no max)
        uint32_t pfrag[4][4];
        #pragma unroll
        for (int c = 0; c < 4; c++) {
            pfrag[c][0] = ex2h2(packh2(sacc[2 * c][0],     sacc[2 * c][1]));
            pfrag[c][1] = ex2h2(packh2(sacc[2 * c][2],     sacc[2 * c][3]));
            pfrag[c][2] = ex2h2(packh2(sacc[2 * c + 1][0], sacc[2 * c + 1][1]));
            pfrag[c][3] = ex2h2(packh2(sacc[2 * c + 1][2], sacc[2 * c + 1][3]));
        }

        // O += P @ V ; l += P @ ones
        #pragma unroll
        for (int c = 0; c < 4; c++) {
            mma16816(lacc, pfrag[c], onesf[0], onesf[1]);
            #pragma unroll
            for (int g = 0; g < 4; g++) {
                uint32_t r4[4];
                int row = c * 16 + rowin;
                ldmx4t(r4, Vcur + (row * 64 + (((2 * g + chsel) ^ (row & 7)) * 8)) * 2);
                mma16816(oacc[2 * g],     pfrag[c], r4[0], r4[1]);
                mma16816(oacc[2 * g + 1], pfrag[c], r4[2], r4[3]);
            }
        }
    }

    // Epilogue: l lives in col 0 (tig==0); broadcast within each quad
    float l0 = __shfl_sync(0xffffffffu, lacc[0], lane & 28);
    float l1 = __shfl_sync(0xffffffffu, lacc[2], lane & 28);
    float inv0 = 1.0f / l0, inv1 = 1.0f / l1;
    size_t row0 = (size_t)(b * N_TOK + n0 + warp * 16 + gid) * DIM_N;
    size_t row1 = row0 + 8 * DIM_N;
    #pragma unroll
    for (int nt = 0; nt < 8; nt++) {
        int col = h * 64 + nt * 8 + tig * 2;
        *(uint32_t*)&g_att[row0 + col] =
            packh2(oacc[nt][0] * inv0, oacc[nt][1] * inv0);
        *(uint32_t*)&g_att[row1 + col] =
            packh2(oacc[nt][2] * inv1, oacc[nt][3] * inv1);
    }
}

// ---------------------------------------------------------------------------
extern "C" void kernel_launch(void* const* d_in, const int* in_sizes, int n_in,
                              void* d_out, int out_size) {
    const float* x           = (const float*)d_in[0];
    const float* ln_w        = (const float*)d_in[1];
    const float* ln_b        = (const float*)d_in[2];
    const float* qkv_w       = (const float*)d_in[3];
    const float* qkv_b       = (const float*)d_in[4];
    const float* proj_w      = (const float*)d_in[5];
    const float* proj_b      = (const float*)d_in[6];
    const float* attn_biases = (const float*)d_in[7];

    void *p_xn, *p_qkv, *p_att, *p_wq, *p_wp;
    cudaGetSymbolAddress(&p_xn, g_xn);
    cudaGetSymbolAddress(&p_qkv, g_qkv);
    cudaGetSymbolAddress(&p_att, g_att);
    cudaGetSymbolAddress(&p_wq, g_wq);
    cudaGetSymbolAddress(&p_wp, g_wp);

    cudaFuncSetAttribute(hgemm_bias<1>,
                         cudaFuncAttributeMaxDynamicSharedMemorySize, G_SMEM);
    cudaFuncSetAttribute(hgemm_bias<0>,
                         cudaFuncAttributeMaxDynamicSharedMemorySize, G_SMEM);
    cudaFuncSetAttribute(attn_kernel,
                         cudaFuncAttributeMaxDynamicSharedMemorySize, ATTN_SMEM);

    // 0. Weight conversion fp32 -> fp16
    cvt_f2h<<<(QKVD * DIM_N / 4 + 255) / 256, 256>>>(qkv_w, (__half*)p_wq,
                                                     QKVD * DIM_N);
    cvt_f2h<<<(DIM_N * DIM_N / 4 + 255) / 256, 256>>>(proj_w, (__half*)p_wp,
                                                      DIM_N * DIM_N);

    // 1. LayerNorm -> fp16
    ln_kernel<<<MROWS, 256>>>(x, ln_w, ln_b);

    // 2. QKV GEMM (fp16 HMMA): [16384,768] @ [2304,768]^T
    hgemm_bias<1><<<dim3(QKVD / 128, MROWS / 128), 256, G_SMEM>>>(
        (const __half*)p_xn, (const __half*)p_wq, qkv_b, p_qkv,
        MROWS, QKVD, DIM_N);

    // 3. Fused attention (static-shift softmax, hoisted bias indexing)
    attn_kernel<<<dim3(N_TOK / 128, H_N, B_N), 256, ATTN_SMEM>>>(attn_biases);

    // 4. Projection GEMM (fp16 HMMA) -> fp32 output
    hgemm_bias<0><<<dim3(DIM_N / 128, MROWS / 128), 256, G_SMEM>>>(
        (const __half*)p_att, (const __half*)p_wp, proj_b, d_out,
        MROWS, DIM_N, DIM_N);
}

// round 11
// speedup vs baseline: 1.4544x; 1.0318x over previous
#include <cuda_runtime.h>
#include <cuda_fp16.h>
#include <math.h>
#include <stdint.h>

// Problem constants
#define B_N   16
#define N_TOK 1024
#define DIM_N 768
#define H_N   12
#define QKVD  2304
#define MROWS 16384
#define SCALE_C 0.125f
#define LOG2E 1.4426950408889634f
#define MSHIFT 4.0f
#define LN_EPS  1e-5f

// Scratch (device globals — no dynamic allocation allowed). All fp16.
__device__ __half g_xn[(size_t)MROWS * DIM_N];
__device__ __half g_qkv[(size_t)MROWS * QKVD];
__device__ __half g_att[(size_t)MROWS * DIM_N];
__device__ __half g_wq[(size_t)QKVD * DIM_N];
__device__ __half g_wp[(size_t)DIM_N * DIM_N];

// ---------------------------------------------------------------------------
// PTX helpers
// ---------------------------------------------------------------------------
__device__ __forceinline__ uint32_t sptr(const void* p) {
    return (uint32_t)__cvta_generic_to_shared(p);
}
__device__ __forceinline__ void ldmx4(uint32_t* r, uint32_t a) {
    asm volatile("ldmatrix.sync.aligned.m8n8.x4.shared.b16 {%0,%1,%2,%3}, [%4];"
                 : "=r"(r[0]), "=r"(r[1]), "=r"(r[2]), "=r"(r[3]) : "r"(a));
}
__device__ __forceinline__ void ldmx4t(uint32_t* r, uint32_t a) {
    asm volatile("ldmatrix.sync.aligned.m8n8.x4.trans.shared.b16 {%0,%1,%2,%3}, [%4];"
                 : "=r"(r[0]), "=r"(r[1]), "=r"(r[2]), "=r"(r[3]) : "r"(a));
}
__device__ __forceinline__ void mma16816(float* c, const uint32_t* a,
                                         uint32_t b0, uint32_t b1) {
    asm volatile(
        "mma.sync.aligned.m16n8k16.row.col.f32.f16.f16.f32 "
        "{%0,%1,%2,%3}, {%4,%5,%6,%7}, {%8,%9}, {%0,%1,%2,%3};"
        : "+f"(c[0]), "+f"(c[1]), "+f"(c[2]), "+f"(c[3])
        : "r"(a[0]), "r"(a[1]), "r"(a[2]), "r"(a[3]), "r"(b0), "r"(b1));
}
__device__ __forceinline__ uint32_t packh2(float x, float y) {
    __half2 h = __floats2half2_rn(x, y);
    return *(uint32_t*)&h;
}
__device__ __forceinline__ uint32_t ex2h2(uint32_t x) {
    uint32_t r;
    asm("ex2.approx.f16x2 %0, %1;" : "=r"(r) : "r"(x));
    return r;
}
#define CP_ASYNC(dst, src) \
    asm volatile("cp.async.cg.shared.global [%0], [%1], 16;" :: "r"(dst), "l"(src))
#define CP_COMMIT() asm volatile("cp.async.commit_group;")
#define CP_WAITN(n) asm volatile("cp.async.wait_group %0;" :: "n"(n))

// ---------------------------------------------------------------------------
// Kernel 0: fp32 -> fp16 weight conversion
// ---------------------------------------------------------------------------
__global__ void cvt_f2h(const float* __restrict__ s, __half* __restrict__ d,
                        int n) {
    int i = (blockIdx.x * 256 + threadIdx.x) * 4;
    if (i < n) {
        float4 v = *(const float4*)(s + i);
        *(__half2*)(d + i)     = __floats2half2_rn(v.x, v.y);
        *(__half2*)(d + i + 2) = __floats2half2_rn(v.z, v.w);
    }
}

// ---------------------------------------------------------------------------
// Kernel 1: LayerNorm -> fp16 output. One block per row. 256 threads.
// ---------------------------------------------------------------------------
__global__ void ln_kernel(const float* __restrict__ x,
                          const float* __restrict__ w,
                          const float* __restrict__ b) {
    int row = blockIdx.x;
    const float* xr = x + (size_t)row * DIM_N;
    int t = threadIdx.x;
    float v0 = xr[t], v1 = xr[t + 256], v2 = xr[t + 512];
    float s  = v0 + v1 + v2;
    float sq = v0 * v0 + v1 * v1 + v2 * v2;
    #pragma unroll
    for (int o = 16; o; o >>= 1) {
        s  += __shfl_xor_sync(0xffffffffu, s, o);
        sq += __shfl_xor_sync(0xffffffffu, sq, o);
    }
    __shared__ float ss[8], ssq[8];
    int wid = t >> 5, lid = t & 31;
    if (lid == 0) { ss[wid] = s; ssq[wid] = sq; }
    __syncthreads();
    if (wid == 0) {
        s = ss[lid & 7]; sq = ssq[lid & 7];
        #pragma unroll
        for (int o = 4; o; o >>= 1) {
            s  += __shfl_xor_sync(0xffffffffu, s, o);
            sq += __shfl_xor_sync(0xffffffffu, sq, o);
        }
        if (lid == 0) { ss[0] = s; ssq[0] = sq; }
    }
    __syncthreads();
    float mean = ss[0] * (1.0f / DIM_N);
    float var  = ssq[0] * (1.0f / DIM_N) - mean * mean;
    float rstd = rsqrtf(var + LN_EPS);
    __half* o = g_xn + (size_t)row * DIM_N;
    int c = t;
    o[c] = __float2half((v0 - mean) * rstd * w[c] + b[c]); c += 256;
    o[c] = __float2half((v1 - mean) * rstd * w[c] + b[c]); c += 256;
    o[c] = __float2half((v2 - mean) * rstd * w[c] + b[c]);
}

// ---------------------------------------------------------------------------
// Kernel 2/4: fp16 HMMA GEMM  C[M,J] = A[M,K] @ W[J,K]^T + bias[J]
// 128x128 tile, BK=64, 8 warps (2x4), warp 64x32, 3-stage cp.async ring,
// one barrier per chunk; B-fragment ping-pong across ks-steps.
// ---------------------------------------------------------------------------
#define G_STGB 32768            // per stage: A 16KB + B 16KB
#define G_SMEM (3 * G_STGB)     // 96 KB

template <int OUT_HALF>
__global__ void __launch_bounds__(256, 2)
hgemm_bias(const __half* __restrict__ A, const __half* __restrict__ W,
           const float* __restrict__ bias, void* __restrict__ Cv,
           int M, int J, int K) {
    extern __shared__ __align__(1024) char smg[];
    uint32_t sb = sptr(smg);

    int m0 = blockIdx.y * 128, j0 = blockIdx.x * 128;
    int tid = threadIdx.x, warp = tid >> 5, lane = tid & 31;
    int gid = lane >> 2, tig = lane & 3;
    int wm = (warp >> 2) * 64, wn = (warp & 3) * 32;
    int lr = tid >> 1, side = tid & 1;

    const __half* Ap = A + (size_t)(m0 + lr) * K + side * 32;
    const __half* Wp = W + (size_t)(j0 + lr) * K + side * 32;

    uint32_t sw[4];
    #pragma unroll
    for (int j = 0; j < 4; j++) {
        int c = side * 4 + j;
        sw[j] = (lr * 64 + ((c ^ (lr & 7)) * 8)) * 2;
    }

    auto fill = [&](int c, int s) {
        uint32_t as = sb + s * G_STGB;
        uint32_t bs = as + 16384;
        #pragma unroll
        for (int j = 0; j < 4; j++) {
            CP_ASYNC(as + sw[j], Ap + c * 64 + 8 * j);
            CP_ASYNC(bs + sw[j], Wp + c * 64 + 8 * j);
        }
        CP_COMMIT();
    };

    int tile = lane >> 3, rlow = lane & 7;
    int rowin = (tile & 1) * 8 + rlow;
    int chsel = tile >> 1;

    float acc[4][4][4];
    #pragma unroll
    for (int mt = 0; mt < 4; mt++)
        #pragma unroll
        for (int nt = 0; nt < 4; nt++)
            #pragma unroll
            for (int e = 0; e < 4; e++) acc[mt][nt][e] = 0.0f;

    int nk = K / 64;                 // 12
    fill(0, 0); fill(1, 1); fill(2, 2);

    for (int i = 0; i < nk; i++) {
        if (i == 0)           { CP_WAITN(2); }
        else if (i < nk - 1)  { CP_WAITN(1); }
        else                  { CP_WAITN(0); }
        __syncthreads();
        if (i >= 1 && i + 2 < nk) fill(i + 2, (i + 2) % 3);

        int s = i - (i / 3) * 3;
        uint32_t Ab = sb + s * G_STGB, Bb = Ab + 16384;

        uint32_t bfr[2][8];
        {
            int ch0 = (chsel ^ rlow) * 8;   // ks = 0
            ldmx4(&bfr[0][0], Bb + ((wn + rowin) * 64 + ch0) * 2);
            ldmx4(&bfr[0][4], Bb + ((wn + 16 + rowin) * 64 + ch0) * 2);
        }
        #pragma unroll
        for (int ks = 0; ks < 4; ks++) {
            int cur = ks & 1;
            int chunk = ((2 * ks + chsel) ^ rlow) * 8;
            uint32_t af[4][4];
            #pragma unroll
            for (int mt = 0; mt < 4; mt++)
                ldmx4(af[mt], Ab + ((wm + mt * 16 + rowin) * 64 + chunk) * 2);
            if (ks < 3) {
                int chn = ((2 * (ks + 1) + chsel) ^ rlow) * 8;
                ldmx4(&bfr[cur ^ 1][0], Bb + ((wn + rowin) * 64 + chn) * 2);
                ldmx4(&bfr[cur ^ 1][4], Bb + ((wn + 16 + rowin) * 64 + chn) * 2);
            }
            #pragma unroll
            for (int g = 0; g < 2; g++) {
                const uint32_t* r4 = &bfr[cur][g * 4];
                #pragma unroll
                for (int mt = 0; mt < 4; mt++) {
                    mma16816(acc[mt][2 * g],     af[mt], r4[0], r4[2]);
                    mma16816(acc[mt][2 * g + 1], af[mt], r4[1], r4[3]);
                }
            }
        }
    }

    // Epilogue
    #pragma unroll
    for (int mt = 0; mt < 4; mt++) {
        int row0 = m0 + wm + mt * 16 + gid;
        #pragma unroll
        for (int nt = 0; nt < 4; nt++) {
            int col = j0 + wn + nt * 8 + tig * 2;
            float b0 = bias[col], b1 = bias[col + 1];
            if (OUT_HALF) {
                __half* C = (__half*)Cv;
                *(uint32_t*)&C[(size_t)row0 * J + col] =
                    packh2(acc[mt][nt][0] + b0, acc[mt][nt][1] + b1);
                *(uint32_t*)&C[(size_t)(row0 + 8) * J + col] =
                    packh2(acc[mt][nt][2] + b0, acc[mt][nt][3] + b1);
            } else {
                float* C = (float*)Cv;
                *(float2*)&C[(size_t)row0 * J + col] =
                    make_float2(acc[mt][nt][0] + b0, acc[mt][nt][1] + b1);
                *(float2*)&C[(size_t)(row0 + 8) * J + col] =
                    make_float2(acc[mt][nt][2] + b0, acc[mt][nt][3] + b1);
            }
        }
    }
}

// ---------------------------------------------------------------------------
// Kernel 3: fused flash attention, fp16 MMA.
// Static-shift log2 softmax, hoisted bias indexing, hoisted Q fragments.
// Key tile split into two 32-key halves, issue-order pipelined:
//   S_A -> S_B -> softmax_A (overlaps S_B drain) -> PV_A
//       -> softmax_B (overlaps PV_A drain) -> PV_B
// smem: Q 16K | K 3x8K | V 3x8K | bias 32x33 f32 (4224B) | ones 512B
// ---------------------------------------------------------------------------
#define ATTN_SMEM 70400

__global__ void __launch_bounds__(256, 2)
attn_kernel(const float* __restrict__ biases) {
    extern __shared__ __align__(1024) char sma[];
    __half* Qh     = (__half*)sma;
    float*  b_s    = (float*)(sma + 65536);       // transposed: [dx*33 + dy]
    __half* ones_h = (__half*)(sma + 69824);
    uint32_t Qb = sptr(sma);
    uint32_t Kb = Qb + 16384;   // 3 stages of 8192 B
    uint32_t Vb = Qb + 40960;   // 3 stages of 8192 B
    uint32_t Ob = Qb + 69824;

    int qt = blockIdx.x, h = blockIdx.y, b = blockIdx.z;
    int tid = threadIdx.x, warp = tid >> 5, lane = tid & 31;
    int gid = lane >> 2, tig = lane & 3;
    int n0 = qt * 128;
    const float SCALE2 = SCALE_C * LOG2E;

    // bias table: transposed, stride 33, with log2e scale and -MSHIFT folded
    for (int i = tid; i < 1024; i += 256) {
        int dy = i >> 5, dx = i & 31;
        b_s[dx * 33 + dy] = biases[h * 1024 + i] * LOG2E - MSHIFT;
    }

    // Stage Q [128 rows][64 dims], swizzled
    {
        int r = tid >> 1, side = tid & 1;
        const __half* qp = g_qkv + (size_t)(b * N_TOK + n0 + r) * QKVD
                           + h * 192 + side * 32;
        #pragma unroll
        for (int j = 0; j < 4; j++) {
            int c = side * 4 + j;
            *(uint4*)&Qh[r * 64 + ((c ^ (r & 7)) * 8)] =
                *(const uint4*)(qp + 8 * j);
        }
    }
    // ones tile [16 keys][16 dims], col 0 = 1
    if (tid < 16) {
        #pragma unroll
        for (int c = 0; c < 16; c++)
            ones_h[tid * 16 + c] = (c == 0) ? __float2half(1.0f)
                                            : __float2half(0.0f);
    }

    int tile = lane >> 3, rlow = lane & 7;
    int rowin = (tile & 1) * 8 + rlow;
    int chsel = tile >> 1;

    __syncthreads();
    uint32_t onesf[4];
    ldmx4t(onesf, Ob + rowin * 32 + chsel * 16);

    // Hoisted Q fragments (invariant across key tiles)
    uint32_t qfrag[4][4];
    #pragma unroll
    for (int ks = 0; ks < 4; ks++) {
        int chunk = ((2 * ks + chsel) ^ rlow) * 8;
        ldmx4(qfrag[ks], Qb + ((warp * 16 + rowin) * 64 + chunk) * 2);
    }

    // Precomputed dx*33 tables: v = (nt&3)*2 + e -> xm = (v>>1)*8 + tig*2 + (v&1)
    int q0 = n0 + warp * 16 + gid, q1 = q0 + 8;
    int yq0 = q0 >> 5, xq0 = q0 & 31;
    int yq1 = q1 >> 5, xq1 = q1 & 31;
    int dx0t[8], dx1t[8];
    #pragma unroll
    for (int v = 0; v < 8; v++) {
        int xm = (v >> 1) * 8 + tig * 2 + (v & 1);
        dx0t[v] = abs(xq0 - xm) * 33;
        dx1t[v] = abs(xq1 - xm) * 33;
    }

    // K/V fill via cp.async (3-stage ring)
    int fr = tid >> 2, fq = tid & 3;
    uint32_t fsw[2];
    #pragma unroll
    for (int j = 0; j < 2; j++) {
        int c = fq * 2 + j;
        fsw[j] = (fr * 64 + ((c ^ (fr & 7)) * 8)) * 2;
    }
    auto fillkv = [&](int kt, int s) {
        const __half* kp = g_qkv + (size_t)(b * N_TOK + kt * 64 + fr) * QKVD
                           + h * 192 + 64 + fq * 16;
        const __half* vp = kp + 64;
        #pragma unroll
        for (int j = 0; j < 2; j++) {
            CP_ASYNC(Kb + s * 8192 + fsw[j], kp + 8 * j);
            CP_ASYNC(Vb + s * 8192 + fsw[j], vp + 8 * j);
        }
        CP_COMMIT();
    };

    float oacc[8][4], lacc[4];
    #pragma unroll
    for (int nt = 0; nt < 8; nt++)
        #pragma unroll
        for (int e = 0; e < 4; e++) oacc[nt][e] = 0.0f;
    #pragma unroll
    for (int e = 0; e < 4; e++) lacc[e] = 0.0f;

    fillkv(0, 0); fillkv(1, 1);

    for (int kt = 0; kt < 16; kt++) {
        if (kt < 15) { CP_WAITN(1); }
        else         { CP_WAITN(0); }
        __syncthreads();
        if (kt + 2 < 16) fillkv(kt + 2, (kt + 2) % 3);

        int s = kt - (kt / 3) * 3;
        uint32_t Kcur = Kb + s * 8192;
        uint32_t Vcur = Vb + s * 8192;

        float sacc[8][4];
        #pragma unroll
        for (int nt = 0; nt < 8; nt++)
            #pragma unroll
            for (int e = 0; e < 4; e++) sacc[nt][e] = 0.0f;

        // ---- S_A: keys 0..31 (n-tile groups g=0,1) ----
        #pragma unroll
        for (int ks = 0; ks < 4; ks++) {
            int chunk = ((2 * ks + chsel) ^ rlow) * 8;
            #pragma unroll
            for (int g = 0; g < 2; g++) {
                uint32_t r4[4];
                ldmx4(r4, Kcur + ((g * 16 + rowin) * 64 + chunk) * 2);
                mma16816(sacc[2 * g],     qfrag[ks], r4[0], r4[2]);
                mma16816(sacc[2 * g + 1], qfrag[ks], r4[1], r4[3]);
            }
        }
        // ---- S_B: keys 32..63 (g=2,3) ----
        #pragma unroll
        for (int ks = 0; ks < 4; ks++) {
            int chunk = ((2 * ks + chsel) ^ rlow) * 8;
            #pragma unroll
            for (int g = 2; g < 4; g++) {
                uint32_t r4[4];
                ldmx4(r4, Kcur + ((g * 16 + rowin) * 64 + chunk) * 2);
                mma16816(sacc[2 * g],     qfrag[ks], r4[0], r4[2]);
                mma16816(sacc[2 * g + 1], qfrag[ks], r4[1], r4[3]);
            }
        }

        // ---- softmax_A (ym = 2kt; overlaps S_B MMA drain) ----
        int dy0A = abs(yq0 - 2 * kt), dy1A = abs(yq1 - 2 * kt);
        #pragma unroll
        for (int nt = 0; nt < 4; nt++) {
            #pragma unroll
            for (int e = 0; e < 2; e++) {
                int v = nt * 2 + e;
                sacc[nt][e]     = sacc[nt][e]     * SCALE2 + b_s[dx0t[v] + dy0A];
                sacc[nt][e + 2] = sacc[nt][e + 2] * SCALE2 + b_s[dx1t[v] + dy1A];
            }
        }
        uint32_t pfragA[2][4];
        #pragma unroll
        for (int c = 0; c < 2; c++) {
            pfragA[c][0] = ex2h2(packh2(sacc[2 * c][0],     sacc[2 * c][1]));
            pfragA[c][1] = ex2h2(packh2(sacc[2 * c][2],     sacc[2 * c][3]));
            pfragA[c][2] = ex2h2(packh2(sacc[2 * c + 1][0], sacc[2 * c + 1][1]));
            pfragA[c][3] = ex2h2(packh2(sacc[2 * c + 1][2], sacc[2 * c + 1][3]));
        }

        // ---- PV_A: key chunks c=0,1 ----
        #pragma unroll
        for (int c = 0; c < 2; c++) {
            mma16816(lacc, pfragA[c], onesf[0], onesf[1]);
            #pragma unroll
            for (int g = 0; g < 4; g++) {
                uint32_t r4[4];
                int row = c * 16 + rowin;
                ldmx4t(r4, Vcur + (row * 64 + (((2 * g + chsel) ^ (row & 7)) * 8)) * 2);
                mma16816(oacc[2 * g],     pfragA[c], r4[0], r4[1]);
                mma16816(oacc[2 * g + 1], pfragA[c], r4[2], r4[3]);
            }
        }

        // ---- softmax_B (ym = 2kt+1; overlaps PV_A MMA drain) ----
        int dy0B = abs(yq0 - 2 * kt - 1), dy1B = abs(yq1 - 2 * kt - 1);
        #pragma unroll
        for (int nt = 4; nt < 8; nt++) {
            #pragma unroll
            for (int e = 0; e < 2; e++) {
                int v = (nt & 3) * 2 + e;
                sacc[nt][e]     = sacc[nt][e]     * SCALE2 + b_s[dx0t[v] + dy0B];
                sacc[nt][e + 2] = sacc[nt][e + 2] * SCALE2 + b_s[dx1t[v] + dy1B];
            }
        }
        uint32_t pfragB[2][4];
        #pragma unroll
        for (int c = 0; c < 2; c++) {
            pfragB[c][0] = ex2h2(packh2(sacc[4 + 2 * c][0],     sacc[4 + 2 * c][1]));
            pfragB[c][1] = ex2h2(packh2(sacc[4 + 2 * c][2],     sacc[4 + 2 * c][3]));
            pfragB[c][2] = ex2h2(packh2(sacc[5 + 2 * c][0],     sacc[5 + 2 * c][1]));
            pfragB[c][3] = ex2h2(packh2(sacc[5 + 2 * c][2],     sacc[5 + 2 * c][3]));
        }

        // ---- PV_B: key chunks c=2,3 ----
        #pragma unroll
        for (int c = 0; c < 2; c++) {
            mma16816(lacc, pfragB[c], onesf[0], onesf[1]);
            #pragma unroll
            for (int g = 0; g < 4; g++) {
                uint32_t r4[4];
                int row = (c + 2) * 16 + rowin;
                ldmx4t(r4, Vcur + (row * 64 + (((2 * g + chsel) ^ (row & 7)) * 8)) * 2);
                mma16816(oacc[2 * g],     pfragB[c], r4[0], r4[1]);
                mma16816(oacc[2 * g + 1], pfragB[c], r4[2], r4[3]);
            }
        }
    }

    // Epilogue: l lives in col 0 (tig==0); broadcast within each quad
    float l0 = __shfl_sync(0xffffffffu, lacc[0], lane & 28);
    float l1 = __shfl_sync(0xffffffffu, lacc[2], lane & 28);
    float inv0 = 1.0f / l0, inv1 = 1.0f / l1;
    size_t row0 = (size_t)(b * N_TOK + n0 + warp * 16 + gid) * DIM_N;
    size_t row1 = row0 + 8 * DIM_N;
    #pragma unroll
    for (int nt = 0; nt < 8; nt++) {
        int col = h * 64 + nt * 8 + tig * 2;
        *(uint32_t*)&g_att[row0 + col] =
            packh2(oacc[nt][0] * inv0, oacc[nt][1] * inv0);
        *(uint32_t*)&g_att[row1 + col] =
            packh2(oacc[nt][2] * inv1, oacc[nt][3] * inv1);
    }
}

// ---------------------------------------------------------------------------
extern "C" void kernel_launch(void* const* d_in, const int* in_sizes, int n_in,
                              void* d_out, int out_size) {
    const float* x           = (const float*)d_in[0];
    const float* ln_w        = (const float*)d_in[1];
    const float* ln_b        = (const float*)d_in[2];
    const float* qkv_w       = (const float*)d_in[3];
    const float* qkv_b       = (const float*)d_in[4];
    const float* proj_w      = (const float*)d_in[5];
    const float* proj_b      = (const float*)d_in[6];
    const float* attn_biases = (const float*)d_in[7];

    void *p_xn, *p_qkv, *p_att, *p_wq, *p_wp;
    cudaGetSymbolAddress(&p_xn, g_xn);
    cudaGetSymbolAddress(&p_qkv, g_qkv);
    cudaGetSymbolAddress(&p_att, g_att);
    cudaGetSymbolAddress(&p_wq, g_wq);
    cudaGetSymbolAddress(&p_wp, g_wp);

    cudaFuncSetAttribute(hgemm_bias<1>,
                         cudaFuncAttributeMaxDynamicSharedMemorySize, G_SMEM);
    cudaFuncSetAttribute(hgemm_bias<0>,
                         cudaFuncAttributeMaxDynamicSharedMemorySize, G_SMEM);
    cudaFuncSetAttribute(attn_kernel,
                         cudaFuncAttributeMaxDynamicSharedMemorySize, ATTN_SMEM);

    // 0. Weight conversion fp32 -> fp16
    cvt_f2h<<<(QKVD * DIM_N / 4 + 255) / 256, 256>>>(qkv_w, (__half*)p_wq,
                                                     QKVD * DIM_N);
    cvt_f2h<<<(DIM_N * DIM_N / 4 + 255) / 256, 256>>>(proj_w, (__half*)p_wp,
                                                      DIM_N * DIM_N);

    // 1. LayerNorm -> fp16
    ln_kernel<<<MROWS, 256>>>(x, ln_w, ln_b);

    // 2. QKV GEMM (fp16 HMMA): [16384,768] @ [2304,768]^T
    hgemm_bias<1><<<dim3(QKVD / 128, MROWS / 128), 256, G_SMEM>>>(
        (const __half*)p_xn, (const __half*)p_wq, qkv_b, p_qkv,
        MROWS, QKVD, DIM_N);

    // 3. Fused attention (half-tile pipelined softmax/MMA)
    attn_kernel<<<dim3(N_TOK / 128, H_N, B_N), 256, ATTN_SMEM>>>(attn_biases);

    // 4. Projection GEMM (fp16 HMMA) -> fp32 output
    hgemm_bias<0><<<dim3(DIM_N / 128, MROWS / 128), 256, G_SMEM>>>(
        (const __half*)p_att, (const __half*)p_wp, proj_b, d_out,
        MROWS, DIM_N, DIM_N);
}

// round 12
// speedup vs baseline: 1.4716x; 1.0118x over previous
#include <cuda_runtime.h>
#include <cuda_fp16.h>
#include <math.h>
#include <stdint.h>

// Problem constants
#define B_N   16
#define N_TOK 1024
#define DIM_N 768
#define H_N   12
#define QKVD  2304
#define MROWS 16384
#define SCALE_C 0.125f
#define LOG2E 1.4426950408889634f
#define MSHIFT 4.0f
#define LN_EPS  1e-5f

// Scratch (device globals — no dynamic allocation allowed). All fp16.
__device__ __half g_xn[(size_t)MROWS * DIM_N];
__device__ __half g_qkv[(size_t)MROWS * QKVD];
__device__ __half g_att[(size_t)MROWS * DIM_N];
__device__ __half g_wq[(size_t)QKVD * DIM_N];
__device__ __half g_wp[(size_t)DIM_N * DIM_N];

// ---------------------------------------------------------------------------
// PTX helpers
// ---------------------------------------------------------------------------
__device__ __forceinline__ uint32_t sptr(const void* p) {
    return (uint32_t)__cvta_generic_to_shared(p);
}
__device__ __forceinline__ void ldmx4(uint32_t* r, uint32_t a) {
    asm volatile("ldmatrix.sync.aligned.m8n8.x4.shared.b16 {%0,%1,%2,%3}, [%4];"
                 : "=r"(r[0]), "=r"(r[1]), "=r"(r[2]), "=r"(r[3]) : "r"(a));
}
__device__ __forceinline__ void ldmx4t(uint32_t* r, uint32_t a) {
    asm volatile("ldmatrix.sync.aligned.m8n8.x4.trans.shared.b16 {%0,%1,%2,%3}, [%4];"
                 : "=r"(r[0]), "=r"(r[1]), "=r"(r[2]), "=r"(r[3]) : "r"(a));
}
__device__ __forceinline__ void mma16816(float* c, const uint32_t* a,
                                         uint32_t b0, uint32_t b1) {
    asm volatile(
        "mma.sync.aligned.m16n8k16.row.col.f32.f16.f16.f32 "
        "{%0,%1,%2,%3}, {%4,%5,%6,%7}, {%8,%9}, {%0,%1,%2,%3};"
        : "+f"(c[0]), "+f"(c[1]), "+f"(c[2]), "+f"(c[3])
        : "r"(a[0]), "r"(a[1]), "r"(a[2]), "r"(a[3]), "r"(b0), "r"(b1));
}
__device__ __forceinline__ uint32_t packh2(float x, float y) {
    __half2 h = __floats2half2_rn(x, y);
    return *(uint32_t*)&h;
}
__device__ __forceinline__ uint32_t ex2h2(uint32_t x) {
    uint32_t r;
    asm("ex2.approx.f16x2 %0, %1;" : "=r"(r) : "r"(x));
    return r;
}
#define CP_ASYNC(dst, src) \
    asm volatile("cp.async.cg.shared.global [%0], [%1], 16;" :: "r"(dst), "l"(src))
#define CP_COMMIT() asm volatile("cp.async.commit_group;")
#define CP_WAITN(n) asm volatile("cp.async.wait_group %0;" :: "n"(n))

// ---------------------------------------------------------------------------
// Kernel 0: fp32 -> fp16 conversion of BOTH weight matrices (merged launch)
// ---------------------------------------------------------------------------
__global__ void cvt_all(const float* __restrict__ wq_f,
                        const float* __restrict__ wp_f,
                        __half* __restrict__ wq_h,
                        __half* __restrict__ wp_h) {
    const int NQ = QKVD * DIM_N;
    const int NP = DIM_N * DIM_N;
    int i = (blockIdx.x * 256 + threadIdx.x) * 4;
    if (i < NQ) {
        float4 v = *(const float4*)(wq_f + i);
        *(__half2*)(wq_h + i)     = __floats2half2_rn(v.x, v.y);
        *(__half2*)(wq_h + i + 2) = __floats2half2_rn(v.z, v.w);
    } else {
        int k = i - NQ;
        if (k < NP) {
            float4 v = *(const float4*)(wp_f + k);
            *(__half2*)(wp_h + k)     = __floats2half2_rn(v.x, v.y);
            *(__half2*)(wp_h + k + 2) = __floats2half2_rn(v.z, v.w);
        }
    }
}

// ---------------------------------------------------------------------------
// Kernel 1: LayerNorm -> fp16. Warp-per-row, 8 rows per 256-thread block.
// Pure shuffle reduce, float4 loads (6 per lane), no smem / no block sync.
// ---------------------------------------------------------------------------
__global__ void ln_kernel(const float* __restrict__ x,
                          const float* __restrict__ w,
                          const float* __restrict__ b) {
    int warp = threadIdx.x >> 5, lane = threadIdx.x & 31;
    int row = blockIdx.x * 8 + warp;
    const float4* xr = (const float4*)(x + (size_t)row * DIM_N);
    float4 v[6];
    float s = 0.0f, sq = 0.0f;
    #pragma unroll
    for (int j = 0; j < 6; j++) {
        v[j] = xr[lane + 32 * j];
        s  += v[j].x + v[j].y + v[j].z + v[j].w;
        sq += v[j].x * v[j].x + v[j].y * v[j].y
            + v[j].z * v[j].z + v[j].w * v[j].w;
    }
    #pragma unroll
    for (int o = 16; o; o >>= 1) {
        s  += __shfl_xor_sync(0xffffffffu, s, o);
        sq += __shfl_xor_sync(0xffffffffu, sq, o);
    }
    float mean = s * (1.0f / DIM_N);
    float var  = sq * (1.0f / DIM_N) - mean * mean;
    float rstd = rsqrtf(var + LN_EPS);
    uint2* orow = (uint2*)(g_xn + (size_t)row * DIM_N);
    const float4* wv = (const float4*)w;
    const float4* bv = (const float4*)b;
    #pragma unroll
    for (int j = 0; j < 6; j++) {
        int idx = lane + 32 * j;
        float4 wj = wv[idx], bj = bv[idx];
        float o0 = (v[j].x - mean) * rstd * wj.x + bj.x;
        float o1 = (v[j].y - mean) * rstd * wj.y + bj.y;
        float o2 = (v[j].z - mean) * rstd * wj.z + bj.z;
        float o3 = (v[j].w - mean) * rstd * wj.w + bj.w;
        orow[idx] = make_uint2(packh2(o0, o1), packh2(o2, o3));
    }
}

// ---------------------------------------------------------------------------
// Kernel 2/4: fp16 HMMA GEMM  C[M,J] = A[M,K] @ W[J,K]^T + bias[J]
// (unchanged from R11 — control kernel)
// ---------------------------------------------------------------------------
#define G_STGB 32768            // per stage: A 16KB + B 16KB
#define G_SMEM (3 * G_STGB)     // 96 KB

template <int OUT_HALF>
__global__ void __launch_bounds__(256, 2)
hgemm_bias(const __half* __restrict__ A, const __half* __restrict__ W,
           const float* __restrict__ bias, void* __restrict__ Cv,
           int M, int J, int K) {
    extern __shared__ __align__(1024) char smg[];
    uint32_t sb = sptr(smg);

    int m0 = blockIdx.y * 128, j0 = blockIdx.x * 128;
    int tid = threadIdx.x, warp = tid >> 5, lane = tid & 31;
    int gid = lane >> 2, tig = lane & 3;
    int wm = (warp >> 2) * 64, wn = (warp & 3) * 32;
    int lr = tid >> 1, side = tid & 1;

    const __half* Ap = A + (size_t)(m0 + lr) * K + side * 32;
    const __half* Wp = W + (size_t)(j0 + lr) * K + side * 32;

    uint32_t sw[4];
    #pragma unroll
    for (int j = 0; j < 4; j++) {
        int c = side * 4 + j;
        sw[j] = (lr * 64 + ((c ^ (lr & 7)) * 8)) * 2;
    }

    auto fill = [&](int c, int s) {
        uint32_t as = sb + s * G_STGB;
        uint32_t bs = as + 16384;
        #pragma unroll
        for (int j = 0; j < 4; j++) {
            CP_ASYNC(as + sw[j], Ap + c * 64 + 8 * j);
            CP_ASYNC(bs + sw[j], Wp + c * 64 + 8 * j);
        }
        CP_COMMIT();
    };

    int tile = lane >> 3, rlow = lane & 7;
    int rowin = (tile & 1) * 8 + rlow;
    int chsel = tile >> 1;

    float acc[4][4][4];
    #pragma unroll
    for (int mt = 0; mt < 4; mt++)
        #pragma unroll
        for (int nt = 0; nt < 4; nt++)
            #pragma unroll
            for (int e = 0; e < 4; e++) acc[mt][nt][e] = 0.0f;

    int nk = K / 64;                 // 12
    fill(0, 0); fill(1, 1); fill(2, 2);

    for (int i = 0; i < nk; i++) {
        if (i == 0)           { CP_WAITN(2); }
        else if (i < nk - 1)  { CP_WAITN(1); }
        else                  { CP_WAITN(0); }
        __syncthreads();
        if (i >= 1 && i + 2 < nk) fill(i + 2, (i + 2) % 3);

        int s = i - (i / 3) * 3;
        uint32_t Ab = sb + s * G_STGB, Bb = Ab + 16384;

        uint32_t bfr[2][8];
        {
            int ch0 = (chsel ^ rlow) * 8;   // ks = 0
            ldmx4(&bfr[0][0], Bb + ((wn + rowin) * 64 + ch0) * 2);
            ldmx4(&bfr[0][4], Bb + ((wn + 16 + rowin) * 64 + ch0) * 2);
        }
        #pragma unroll
        for (int ks = 0; ks < 4; ks++) {
            int cur = ks & 1;
            int chunk = ((2 * ks + chsel) ^ rlow) * 8;
            uint32_t af[4][4];
            #pragma unroll
            for (int mt = 0; mt < 4; mt++)
                ldmx4(af[mt], Ab + ((wm + mt * 16 + rowin) * 64 + chunk) * 2);
            if (ks < 3) {
                int chn = ((2 * (ks + 1) + chsel) ^ rlow) * 8;
                ldmx4(&bfr[cur ^ 1][0], Bb + ((wn + rowin) * 64 + chn) * 2);
                ldmx4(&bfr[cur ^ 1][4], Bb + ((wn + 16 + rowin) * 64 + chn) * 2);
            }
            #pragma unroll
            for (int g = 0; g < 2; g++) {
                const uint32_t* r4 = &bfr[cur][g * 4];
                #pragma unroll
                for (int mt = 0; mt < 4; mt++) {
                    mma16816(acc[mt][2 * g],     af[mt], r4[0], r4[2]);
                    mma16816(acc[mt][2 * g + 1], af[mt], r4[1], r4[3]);
                }
            }
        }
    }

    // Epilogue
    #pragma unroll
    for (int mt = 0; mt < 4; mt++) {
        int row0 = m0 + wm + mt * 16 + gid;
        #pragma unroll
        for (int nt = 0; nt < 4; nt++) {
            int col = j0 + wn + nt * 8 + tig * 2;
            float b0 = bias[col], b1 = bias[col + 1];
            if (OUT_HALF) {
                __half* C = (__half*)Cv;
                *(uint32_t*)&C[(size_t)row0 * J + col] =
                    packh2(acc[mt][nt][0] + b0, acc[mt][nt][1] + b1);
                *(uint32_t*)&C[(size_t)(row0 + 8) * J + col] =
                    packh2(acc[mt][nt][2] + b0, acc[mt][nt][3] + b1);
            } else {
                float* C = (float*)Cv;
                *(float2*)&C[(size_t)row0 * J + col] =
                    make_float2(acc[mt][nt][0] + b0, acc[mt][nt][1] + b1);
                *(float2*)&C[(size_t)(row0 + 8) * J + col] =
                    make_float2(acc[mt][nt][2] + b0, acc[mt][nt][3] + b1);
            }
        }
    }
}

// ---------------------------------------------------------------------------
// Kernel 3: fused flash attention, fp16 MMA.
// 3-stage ring of 16KB super-stages (2 key-tiles each) -> 8 barrier rounds.
// Static-shift log2 softmax, half-tile softmax/MMA pipelining per key tile,
// constant ones-fragment (no smem), Q staged through V-ring stage 0.
// smem: K 3x16K | V 3x16K | bias 32x33 f32  = 102528 B (2 CTAs/SM)
// ---------------------------------------------------------------------------
#define ATTN_SMEM 102528

__global__ void __launch_bounds__(256, 2)
attn_kernel(const float* __restrict__ biases) {
    extern __shared__ __align__(1024) char sma[];
    float* b_s = (float*)(sma + 98304);           // transposed: [dx*33 + dy]
    uint32_t Kb = sptr(sma);                      // 3 stages x 16384 B
    uint32_t Vb = Kb + 49152;                     // 3 stages x 16384 B
    __half* Qstage = (__half*)(sma + 49152);      // overlays V stage 0

    int qt = blockIdx.x, h = blockIdx.y, b = blockIdx.z;
    int tid = threadIdx.x, warp = tid >> 5, lane = tid & 31;
    int gid = lane >> 2, tig = lane & 3;
    int n0 = qt * 128;
    const float SCALE2 = SCALE_C * LOG2E;

    // bias table: transposed, stride 33, log2e scale and -MSHIFT folded
    for (int i = tid; i < 1024; i += 256) {
        int dy = i >> 5, dx = i & 31;
        b_s[dx * 33 + dy] = biases[h * 1024 + i] * LOG2E - MSHIFT;
    }

    // Stage Q [128 rows][64 dims] into V-ring stage 0 (prologue only)
    {
        int r = tid >> 1, side = tid & 1;
        const __half* qp = g_qkv + (size_t)(b * N_TOK + n0 + r) * QKVD
                           + h * 192 + side * 32;
        #pragma unroll
        for (int j = 0; j < 4; j++) {
            int c = side * 4 + j;
            *(uint4*)&Qstage[r * 64 + ((c ^ (r & 7)) * 8)] =
                *(const uint4*)(qp + 8 * j);
        }
    }
    __syncthreads();

    int tile = lane >> 3, rlow = lane & 7;
    int rowin = (tile & 1) * 8 + rlow;
    int chsel = tile >> 1;

    // Hoisted Q fragments (invariant across key tiles)
    uint32_t qfrag[4][4];
    #pragma unroll
    for (int ks = 0; ks < 4; ks++) {
        int chunk = ((2 * ks + chsel) ^ rlow) * 8;
        ldmx4(qfrag[ks], Vb + ((warp * 16 + rowin) * 64 + chunk) * 2);
    }
    __syncthreads();   // all qfrag extracted before ring overwrites Qstage

    // Constant ones B-fragment: B[k][n] = 1 iff n == 0
    uint32_t ones01 = (gid == 0) ? 0x3C003C00u : 0u;

    // Precomputed dx*33: v = (nt&3)*2 + e -> xm = (v>>1)*8 + tig*2 + (v&1)
    int q0 = n0 + warp * 16 + gid, q1 = q0 + 8;
    int yq0 = q0 >> 5, xq0 = q0 & 31;
    int yq1 = q1 >> 5, xq1 = q1 & 31;
    int dx0t[8], dx1t[8];
    #pragma unroll
    for (int v = 0; v < 8; v++) {
        int xm = (v >> 1) * 8 + tig * 2 + (v & 1);
        dx0t[v] = abs(xq0 - xm) * 33;
        dx1t[v] = abs(xq1 - xm) * 33;
    }

    // K/V super-stage fill: 2 key-tiles (2*j, 2*j+1) per stage s
    int fr = tid >> 2, fq = tid & 3;
    uint32_t fsw[2];
    #pragma unroll
    for (int j = 0; j < 2; j++) {
        int c = fq * 2 + j;
        fsw[j] = (fr * 64 + ((c ^ (fr & 7)) * 8)) * 2;
    }
    auto fillkv2 = [&](int j2, int s) {
        #pragma unroll
        for (int t = 0; t < 2; t++) {
            int kt = 2 * j2 + t;
            const __half* kp = g_qkv + (size_t)(b * N_TOK + kt * 64 + fr) * QKVD
                               + h * 192 + 64 + fq * 16;
            const __half* vp = kp + 64;
            uint32_t off = s * 16384 + t * 8192;
            #pragma unroll
            for (int j = 0; j < 2; j++) {
                CP_ASYNC(Kb + off + fsw[j], kp + 8 * j);
                CP_ASYNC(Vb + off + fsw[j], vp + 8 * j);
            }
        }
        CP_COMMIT();
    };

    float oacc[8][4], lacc[4];
    #pragma unroll
    for (int nt = 0; nt < 8; nt++)
        #pragma unroll
        for (int e = 0; e < 4; e++) oacc[nt][e] = 0.0f;
    #pragma unroll
    for (int e = 0; e < 4; e++) lacc[e] = 0.0f;

    fillkv2(0, 0); fillkv2(1, 1); fillkv2(2, 2);

    for (int j2 = 0; j2 < 8; j2++) {
        if (j2 == 0)      { CP_WAITN(2); }
        else if (j2 < 7)  { CP_WAITN(1); }
        else              { CP_WAITN(0); }
        __syncthreads();
        if (j2 >= 1 && j2 + 2 < 8) fillkv2(j2 + 2, (j2 + 2) % 3);

        int s = j2 - (j2 / 3) * 3;
        #pragma unroll
        for (int t = 0; t < 2; t++) {
            int tt = 2 * j2 + t;        // 64-key tile index 0..15
            uint32_t Kcur = Kb + s * 16384 + t * 8192;
            uint32_t Vcur = Vb + s * 16384 + t * 8192;

            float sacc[8][4];
            #pragma unroll
            for (int nt = 0; nt < 8; nt++)
                #pragma unroll
                for (int e = 0; e < 4; e++) sacc[nt][e] = 0.0f;

            // ---- S_A: keys 0..31 (g=0,1) ----
            #pragma unroll
            for (int ks = 0; ks < 4; ks++) {
                int chunk = ((2 * ks + chsel) ^ rlow) * 8;
                #pragma unroll
                for (int g = 0; g < 2; g++) {
                    uint32_t r4[4];
                    ldmx4(r4, Kcur + ((g * 16 + rowin) * 64 + chunk) * 2);
                    mma16816(sacc[2 * g],     qfrag[ks], r4[0], r4[2]);
                    mma16816(sacc[2 * g + 1], qfrag[ks], r4[1], r4[3]);
                }
            }
            // ---- S_B: keys 32..63 (g=2,3) ----
            #pragma unroll
            for (int ks = 0; ks < 4; ks++) {
                int chunk = ((2 * ks + chsel) ^ rlow) * 8;
                #pragma unroll
                for (int g = 2; g < 4; g++) {
                    uint32_t r4[4];
                    ldmx4(r4, Kcur + ((g * 16 + rowin) * 64 + chunk) * 2);
                    mma16816(sacc[2 * g],     qfrag[ks], r4[0], r4[2]);
                    mma16816(sacc[2 * g + 1], qfrag[ks], r4[1], r4[3]);
                }
            }

            // ---- softmax_A (ym = 2tt) ----
            int dy0A = abs(yq0 - 2 * tt), dy1A = abs(yq1 - 2 * tt);
            #pragma unroll
            for (int nt = 0; nt < 4; nt++) {
                #pragma unroll
                for (int e = 0; e < 2; e++) {
                    int v = nt * 2 + e;
                    sacc[nt][e]     = sacc[nt][e]     * SCALE2 + b_s[dx0t[v] + dy0A];
                    sacc[nt][e + 2] = sacc[nt][e + 2] * SCALE2 + b_s[dx1t[v] + dy1A];
                }
            }
            uint32_t pfragA[2][4];
            #pragma unroll
            for (int c = 0; c < 2; c++) {
                pfragA[c][0] = ex2h2(packh2(sacc[2 * c][0],     sacc[2 * c][1]));
                pfragA[c][1] = ex2h2(packh2(sacc[2 * c][2],     sacc[2 * c][3]));
                pfragA[c][2] = ex2h2(packh2(sacc[2 * c + 1][0], sacc[2 * c + 1][1]));
                pfragA[c][3] = ex2h2(packh2(sacc[2 * c + 1][2], sacc[2 * c + 1][3]));
            }

            // ---- PV_A ----
            #pragma unroll
            for (int c = 0; c < 2; c++) {
                mma16816(lacc, pfragA[c], ones01, ones01);
                #pragma unroll
                for (int g = 0; g < 4; g++) {
                    uint32_t r4[4];
                    int row = c * 16 + rowin;
                    ldmx4t(r4, Vcur + (row * 64 + (((2 * g + chsel) ^ (row & 7)) * 8)) * 2);
                    mma16816(oacc[2 * g],     pfragA[c], r4[0], r4[1]);
                    mma16816(oacc[2 * g + 1], pfragA[c], r4[2], r4[3]);
                }
            }

            // ---- softmax_B (ym = 2tt+1) ----
            int dy0B = abs(yq0 - 2 * tt - 1), dy1B = abs(yq1 - 2 * tt - 1);
            #pragma unroll
            for (int nt = 4; nt < 8; nt++) {
                #pragma unroll
                for (int e = 0; e < 2; e++) {
                    int v = (nt & 3) * 2 + e;
                    sacc[nt][e]     = sacc[nt][e]     * SCALE2 + b_s[dx0t[v] + dy0B];
                    sacc[nt][e + 2] = sacc[nt][e + 2] * SCALE2 + b_s[dx1t[v] + dy1B];
                }
            }
            uint32_t pfragB[2][4];
            #pragma unroll
            for (int c = 0; c < 2; c++) {
                pfragB[c][0] = ex2h2(packh2(sacc[4 + 2 * c][0], sacc[4 + 2 * c][1]));
                pfragB[c][1] = ex2h2(packh2(sacc[4 + 2 * c][2], sacc[4 + 2 * c][3]));
                pfragB[c][2] = ex2h2(packh2(sacc[5 + 2 * c][0], sacc[5 + 2 * c][1]));
                pfragB[c][3] = ex2h2(packh2(sacc[5 + 2 * c][2], sacc[5 + 2 * c][3]));
            }

            // ---- PV_B ----
            #pragma unroll
            for (int c = 0; c < 2; c++) {
                mma16816(lacc, pfragB[c], ones01, ones01);
                #pragma unroll
                for (int g = 0; g < 4; g++) {
                    uint32_t r4[4];
                    int row = (c + 2) * 16 + rowin;
                    ldmx4t(r4, Vcur + (row * 64 + (((2 * g + chsel) ^ (row & 7)) * 8)) * 2);
                    mma16816(oacc[2 * g],     pfragB[c], r4[0], r4[1]);
                    mma16816(oacc[2 * g + 1], pfragB[c], r4[2], r4[3]);
                }
            }
        }
    }

    // Epilogue: l lives in col 0 (tig==0); broadcast within each quad
    float l0 = __shfl_sync(0xffffffffu, lacc[0], lane & 28);
    float l1 = __shfl_sync(0xffffffffu, lacc[2], lane & 28);
    float inv0 = 1.0f / l0, inv1 = 1.0f / l1;
    size_t row0 = (size_t)(b * N_TOK + n0 + warp * 16 + gid) * DIM_N;
    size_t row1 = row0 + 8 * DIM_N;
    #pragma unroll
    for (int nt = 0; nt < 8; nt++) {
        int col = h * 64 + nt * 8 + tig * 2;
        *(uint32_t*)&g_att[row0 + col] =
            packh2(oacc[nt][0] * inv0, oacc[nt][1] * inv0);
        *(uint32_t*)&g_att[row1 + col] =
            packh2(oacc[nt][2] * inv1, oacc[nt][3] * inv1);
    }
}

// ---------------------------------------------------------------------------
extern "C" void kernel_launch(void* const* d_in, const int* in_sizes, int n_in,
                              void* d_out, int out_size) {
    const float* x           = (const float*)d_in[0];
    const float* ln_w        = (const float*)d_in[1];
    const float* ln_b        = (const float*)d_in[2];
    const float* qkv_w       = (const float*)d_in[3];
    const float* qkv_b       = (const float*)d_in[4];
    const float* proj_w      = (const float*)d_in[5];
    const float* proj_b      = (const float*)d_in[6];
    const float* attn_biases = (const float*)d_in[7];

    void *p_xn, *p_qkv, *p_att, *p_wq, *p_wp;
    cudaGetSymbolAddress(&p_xn, g_xn);
    cudaGetSymbolAddress(&p_qkv, g_qkv);
    cudaGetSymbolAddress(&p_att, g_att);
    cudaGetSymbolAddress(&p_wq, g_wq);
    cudaGetSymbolAddress(&p_wp, g_wp);

    cudaFuncSetAttribute(hgemm_bias<1>,
                         cudaFuncAttributeMaxDynamicSharedMemorySize, G_SMEM);
    cudaFuncSetAttribute(hgemm_bias<0>,
                         cudaFuncAttributeMaxDynamicSharedMemorySize, G_SMEM);
    cudaFuncSetAttribute(attn_kernel,
                         cudaFuncAttributeMaxDynamicSharedMemorySize, ATTN_SMEM);

    // 0. Weight conversion fp32 -> fp16 (single merged launch)
    const int NCVT = (QKVD + DIM_N) * DIM_N;
    cvt_all<<<(NCVT / 4 + 255) / 256, 256>>>(qkv_w, proj_w,
                                             (__half*)p_wq, (__half*)p_wp);

    // 1. LayerNorm -> fp16 (warp per row)
    ln_kernel<<<MROWS / 8, 256>>>(x, ln_w, ln_b);

    // 2. QKV GEMM (fp16 HMMA): [16384,768] @ [2304,768]^T
    hgemm_bias<1><<<dim3(QKVD / 128, MROWS / 128), 256, G_SMEM>>>(
        (const __half*)p_xn, (const __half*)p_wq, qkv_b, p_qkv,
        MROWS, QKVD, DIM_N);

    // 3. Fused attention (2 key-tiles per barrier)
    attn_kernel<<<dim3(N_TOK / 128, H_N, B_N), 256, ATTN_SMEM>>>(attn_biases);

    // 4. Projection GEMM (fp16 HMMA) -> fp32 output
    hgemm_bias<0><<<dim3(DIM_N / 128, MROWS / 128), 256, G_SMEM>>>(
        (const __half*)p_att, (const __half*)p_wp, proj_b, d_out,
        MROWS, DIM_N, DIM_N);
}